// round 1
// baseline (speedup 1.0000x reference)
#include <cuda_runtime.h>
#include <math.h>

#define HIDDEN 5120
#define NHEADS 16
#define QLORA  1536
#define KVLORA 512
#define NOPE   128
#define ROPE_D 64
#define QKD    192   // NOPE + ROPE
#define VDIM   128
#define SEQ    2048
#define SM_SCALE 0.07216878364870322f  // 192^-0.5
#define RESID_SCALE 0.125f

// ---------------- scratch (static device arrays; no allocs allowed) ----------
static __device__ float g_h[SEQ * HIDDEN];          // rmsnorm(hidden)
static __device__ float g_qa[SEQ * QLORA];          // q lora (normed in place)
static __device__ float g_q[SEQ * NHEADS * QKD];    // q after up-proj [s][h*192]
static __device__ float g_qf[NHEADS * SEQ * QKD];   // roped Q [h][s][192]
static __device__ float g_ckv[SEQ * (KVLORA + ROPE_D)]; // ckv [s][576]
static __device__ float g_kv[SEQ * NHEADS * (NOPE + VDIM)]; // [s][h*256]
static __device__ float g_attn[SEQ * NHEADS * VDIM];        // [s][h*128]

// ---------------- RMSNorm: one block per row --------------------------------
__global__ void rmsnorm_k(const float* __restrict__ x, const float* __restrict__ w,
                          float* __restrict__ y, int cols, int strideIn, int strideOut)
{
    int row = blockIdx.x;
    int t = threadIdx.x;
    const float* xr = x + (long)row * strideIn;
    float ss = 0.f;
    for (int c = t; c < cols; c += 256) { float v = xr[c]; ss = fmaf(v, v, ss); }
    __shared__ float red[256];
    red[t] = ss; __syncthreads();
    for (int s = 128; s > 0; s >>= 1) { if (t < s) red[t] += red[t + s]; __syncthreads(); }
    float scale = rsqrtf(red[0] / (float)cols + 1e-6f);
    float* yr = y + (long)row * strideOut;
    for (int c = t; c < cols; c += 256) yr[c] = xr[c] * scale * w[c];
}

// ---------------- SGEMM: C[M,N] = A[M,K] * B[N,K]^T (+ beta*D) --------------
// BM=BN=128, BK=8, 256 threads, 8x8 per thread (split 64/64 tiles).
__global__ __launch_bounds__(256, 2)
void sgemm_nt(const float* __restrict__ A, int lda,
              const float* __restrict__ B,
              float* __restrict__ C,
              int M, int N, int K,
              const float* __restrict__ D, float beta)
{
    __shared__ __align__(16) float As[8][132];
    __shared__ __align__(16) float Bs[8][132];

    int t  = threadIdx.x;
    int tx = t & 15, ty = t >> 4;
    int m0 = blockIdx.y * 128, n0 = blockIdx.x * 128;

    int lrow = t >> 1;            // 0..127
    int lk   = (t & 1) * 4;       // 0 or 4
    const float* Ap = A + (long)(m0 + lrow) * lda + lk;
    int brow = n0 + lrow;
    bool bvalid = brow < N;
    const float* Bp = B + (long)brow * K + lk;

    float acc[8][8];
#pragma unroll
    for (int i = 0; i < 8; i++)
#pragma unroll
        for (int j = 0; j < 8; j++) acc[i][j] = 0.f;

    int nk = K >> 3;
    float4 pa = *(const float4*)Ap;
    float4 pb = bvalid ? *(const float4*)Bp : make_float4(0.f, 0.f, 0.f, 0.f);

    for (int kt = 0; kt < nk; ++kt) {
        As[lk + 0][lrow] = pa.x; As[lk + 1][lrow] = pa.y;
        As[lk + 2][lrow] = pa.z; As[lk + 3][lrow] = pa.w;
        Bs[lk + 0][lrow] = pb.x; Bs[lk + 1][lrow] = pb.y;
        Bs[lk + 2][lrow] = pb.z; Bs[lk + 3][lrow] = pb.w;
        __syncthreads();
        if (kt + 1 < nk) {
            Ap += 8; Bp += 8;
            pa = *(const float4*)Ap;
            pb = bvalid ? *(const float4*)Bp : make_float4(0.f, 0.f, 0.f, 0.f);
        }
#pragma unroll
        for (int k = 0; k < 8; ++k) {
            float4 a0 = *(const float4*)&As[k][ty * 4];
            float4 a1 = *(const float4*)&As[k][64 + ty * 4];
            float4 b0 = *(const float4*)&Bs[k][tx * 4];
            float4 b1 = *(const float4*)&Bs[k][64 + tx * 4];
            float av[8] = {a0.x, a0.y, a0.z, a0.w, a1.x, a1.y, a1.z, a1.w};
            float bv[8] = {b0.x, b0.y, b0.z, b0.w, b1.x, b1.y, b1.z, b1.w};
#pragma unroll
            for (int i = 0; i < 8; i++)
#pragma unroll
                for (int j = 0; j < 8; j++)
                    acc[i][j] = fmaf(av[i], bv[j], acc[i][j]);
        }
        __syncthreads();
    }

#pragma unroll
    for (int ih = 0; ih < 2; ih++) {
#pragma unroll
        for (int i = 0; i < 4; i++) {
            int row = m0 + ih * 64 + ty * 4 + i;
#pragma unroll
            for (int jh = 0; jh < 2; jh++) {
                int col = n0 + jh * 64 + tx * 4;
                if (col < N) {
                    float4 v;
                    v.x = acc[ih * 4 + i][jh * 4 + 0];
                    v.y = acc[ih * 4 + i][jh * 4 + 1];
                    v.z = acc[ih * 4 + i][jh * 4 + 2];
                    v.w = acc[ih * 4 + i][jh * 4 + 3];
                    if (D) {
                        float4 dv = *(const float4*)&D[(long)row * N + col];
                        v.x = fmaf(beta, dv.x, v.x);
                        v.y = fmaf(beta, dv.y, v.y);
                        v.z = fmaf(beta, dv.z, v.z);
                        v.w = fmaf(beta, dv.w, v.w);
                    }
                    *(float4*)&C[(long)row * N + col] = v;
                }
            }
        }
    }
}

// ---------------- RoPE + scatter K/V/Q --------------------------------------
__global__ void rope_scatter(const float* __restrict__ qin,  // [s][16*192]
                             const float* __restrict__ ckv,  // [s][576]
                             const float* __restrict__ kvin, // [s][16*256]
                             const int* __restrict__ pos_ids,
                             float* __restrict__ qf,         // [16][s][192]
                             float* __restrict__ kout,       // [16][s][192]
                             float* __restrict__ vout)       // [16][s][128]
{
    int s = blockIdx.x;
    int t = threadIdx.x;
    __shared__ float cs[32], sn[32], kr[64];
    if (t < 32) {
        double invf = exp(-(double)t * 0.28782313662425575); // ln(10000)/32
        double ang = (double)pos_ids[s] * invf;
        cs[t] = (float)cos(ang);
        sn[t] = (float)sin(ang);
    }
    __syncthreads();
    if (t < 32) {
        float x0 = ckv[s * 576 + 512 + 2 * t];
        float x1 = ckv[s * 576 + 512 + 2 * t + 1];
        kr[t]      = x0 * cs[t] - x1 * sn[t];
        kr[32 + t] = x1 * cs[t] + x0 * sn[t];
    }
    __syncthreads();
    // Q rope (pe part) -> qf
    for (int idx = t; idx < 512; idx += 256) {
        int h = idx >> 5, j = idx & 31;
        const float* qb = qin + (long)s * 3072 + h * 192;
        float x0 = qb[128 + 2 * j], x1 = qb[128 + 2 * j + 1];
        float* o = qf + ((long)h * SEQ + s) * 192;
        o[128 + j] = x0 * cs[j] - x1 * sn[j];
        o[160 + j] = x1 * cs[j] + x0 * sn[j];
    }
    // Q nope copy
    for (int idx = t; idx < 2048; idx += 256) {
        int h = idx >> 7, d = idx & 127;
        qf[((long)h * SEQ + s) * 192 + d] = qin[(long)s * 3072 + h * 192 + d];
    }
    // K out
    for (int idx = t; idx < 16 * 192; idx += 256) {
        int h = idx / 192, d = idx - h * 192;
        float v = (d < 128) ? kvin[(long)s * 4096 + h * 256 + d] : kr[d - 128];
        kout[((long)h * SEQ + s) * 192 + d] = v;
    }
    // V out
    for (int idx = t; idx < 2048; idx += 256) {
        int h = idx >> 7, d = idx & 127;
        vout[((long)h * SEQ + s) * 128 + d] = kvin[(long)s * 4096 + h * 256 + 128 + d];
    }
}

// ---------------- flash attention (fp32, causal) ----------------------------
__device__ __forceinline__ float rmax16(float v) {
    v = fmaxf(v, __shfl_xor_sync(0xffffffffu, v, 8));
    v = fmaxf(v, __shfl_xor_sync(0xffffffffu, v, 4));
    v = fmaxf(v, __shfl_xor_sync(0xffffffffu, v, 2));
    v = fmaxf(v, __shfl_xor_sync(0xffffffffu, v, 1));
    return v;
}
__device__ __forceinline__ float rsum16(float v) {
    v += __shfl_xor_sync(0xffffffffu, v, 8);
    v += __shfl_xor_sync(0xffffffffu, v, 4);
    v += __shfl_xor_sync(0xffffffffu, v, 2);
    v += __shfl_xor_sync(0xffffffffu, v, 1);
    return v;
}

#define QS_OFF 0
#define KS_OFF (192 * 68)
#define VS_OFF (2 * 192 * 68)
#define PS_OFF (2 * 192 * 68 + 64 * 132)
#define ATTN_SMEM_BYTES ((2 * 192 * 68 + 64 * 132 + 64 * 68) * 4)

__global__ __launch_bounds__(256, 1)
void flash_attn(const float* __restrict__ Q,  // [16][S][192]
                const float* __restrict__ K,  // [16][S][192]
                const float* __restrict__ V,  // [16][S][128]
                float* __restrict__ O)        // [S][16*128]
{
    extern __shared__ __align__(16) float smf[];
    float* Qs = smf + QS_OFF;   // [192][68] transposed
    float* Ks = smf + KS_OFF;   // [192][68] transposed
    float* Vs = smf + VS_OFF;   // [64][132] row-major
    float* Ps = smf + PS_OFF;   // [64 keys][68 rows]

    int qt = blockIdx.x, h = blockIdx.y;
    int q0 = qt * 64;
    int t = threadIdx.x;
    int tx = t & 15, ty = t >> 4;

    const float* Qg = Q + ((long)h * SEQ + q0) * 192;
    for (int idx = t; idx < 64 * 192; idx += 256) {
        int r = idx / 192, d = idx - r * 192;
        Qs[d * 68 + r] = Qg[idx];
    }

    float mrow[4], lrow[4], acc[4][8];
#pragma unroll
    for (int i = 0; i < 4; i++) {
        mrow[i] = -1e30f; lrow[i] = 0.f;
#pragma unroll
        for (int j = 0; j < 8; j++) acc[i][j] = 0.f;
    }

    const float* Kg = K + (long)h * SEQ * 192;
    const float* Vg = V + (long)h * SEQ * 128;

    for (int kt = 0; kt <= qt; ++kt) {
        int k0 = kt * 64;
        __syncthreads();  // protect Qs(first)/Ks/Vs/Ps from prior use
        for (int idx = t; idx < 64 * 192; idx += 256) {
            int r = idx / 192, d = idx - r * 192;
            Ks[d * 68 + r] = Kg[(long)k0 * 192 + idx];
        }
        for (int idx = t; idx < 64 * 128; idx += 256) {
            Vs[(idx >> 7) * 132 + (idx & 127)] = Vg[(long)k0 * 128 + idx];
        }
        __syncthreads();

        float s[4][4];
#pragma unroll
        for (int i = 0; i < 4; i++)
#pragma unroll
            for (int j = 0; j < 4; j++) s[i][j] = 0.f;

        for (int d = 0; d < 192; ++d) {
            float4 qv = *(const float4*)&Qs[d * 68 + 4 * ty];
            float4 kv = *(const float4*)&Ks[d * 68 + 4 * tx];
            float qa_[4] = {qv.x, qv.y, qv.z, qv.w};
            float kb[4]  = {kv.x, kv.y, kv.z, kv.w};
#pragma unroll
            for (int i = 0; i < 4; i++)
#pragma unroll
                for (int j = 0; j < 4; j++)
                    s[i][j] = fmaf(qa_[i], kb[j], s[i][j]);
        }

#pragma unroll
        for (int i = 0; i < 4; i++)
#pragma unroll
            for (int j = 0; j < 4; j++) s[i][j] *= SM_SCALE;

        if (kt == qt) {
#pragma unroll
            for (int i = 0; i < 4; i++)
#pragma unroll
                for (int j = 0; j < 4; j++)
                    if (k0 + 4 * tx + j > q0 + 4 * ty + i) s[i][j] = -1e30f;
        }

        float p[4][4];
#pragma unroll
        for (int i = 0; i < 4; i++) {
            float mt = fmaxf(fmaxf(s[i][0], s[i][1]), fmaxf(s[i][2], s[i][3]));
            mt = rmax16(mt);
            float mn = fmaxf(mrow[i], mt);
            float al = __expf(mrow[i] - mn);
            mrow[i] = mn;
            float rs = 0.f;
#pragma unroll
            for (int j = 0; j < 4; j++) { p[i][j] = __expf(s[i][j] - mn); rs += p[i][j]; }
            rs = rsum16(rs);
            lrow[i] = lrow[i] * al + rs;
#pragma unroll
            for (int jv = 0; jv < 8; jv++) acc[i][jv] *= al;
        }

#pragma unroll
        for (int j = 0; j < 4; j++) {
            float4 pv = make_float4(p[0][j], p[1][j], p[2][j], p[3][j]);
            *(float4*)&Ps[(4 * tx + j) * 68 + 4 * ty] = pv;
        }
        __syncthreads();

        for (int k = 0; k < 64; ++k) {
            float4 pr = *(const float4*)&Ps[k * 68 + 4 * ty];
            float4 v0 = *(const float4*)&Vs[k * 132 + 8 * tx];
            float4 v1 = *(const float4*)&Vs[k * 132 + 8 * tx + 4];
            float pv[4] = {pr.x, pr.y, pr.z, pr.w};
            float vv[8] = {v0.x, v0.y, v0.z, v0.w, v1.x, v1.y, v1.z, v1.w};
#pragma unroll
            for (int i = 0; i < 4; i++)
#pragma unroll
                for (int j = 0; j < 8; j++)
                    acc[i][j] = fmaf(pv[i], vv[j], acc[i][j]);
        }
    }

#pragma unroll
    for (int i = 0; i < 4; i++) {
        float inv = 1.0f / lrow[i];
        int row = q0 + 4 * ty + i;
        float* op = O + (long)row * 2048 + h * 128 + 8 * tx;
        float4 o0 = make_float4(acc[i][0] * inv, acc[i][1] * inv, acc[i][2] * inv, acc[i][3] * inv);
        float4 o1 = make_float4(acc[i][4] * inv, acc[i][5] * inv, acc[i][6] * inv, acc[i][7] * inv);
        *(float4*)op = o0;
        *(float4*)(op + 4) = o1;
    }
}

// ---------------- launch -----------------------------------------------------
extern "C" void kernel_launch(void* const* d_in, const int* in_sizes, int n_in,
                              void* d_out, int out_size)
{
    const float* hidden   = (const float*)d_in[0];
    const int*   pos      = (const int*)d_in[1];
    // d_in[2] attention_mask: exactly causal 0/-1e9; applied structurally.
    const float* ln_w     = (const float*)d_in[3];
    const float* wq_a     = (const float*)d_in[4];
    const float* q_a_ln   = (const float*)d_in[5];
    const float* wq_b     = (const float*)d_in[6];
    const float* wkv_a    = (const float*)d_in[7];
    const float* kv_a_ln  = (const float*)d_in[8];
    const float* wkv_b    = (const float*)d_in[9];
    const float* wo       = (const float*)d_in[10];

    float* out   = (float*)d_out;
    float* k_out = out + (long)SEQ * HIDDEN;               // [16][2048][192]
    float* v_out = k_out + (long)NHEADS * SEQ * QKD;       // [16][2048][128]

    float *p_h, *p_qa, *p_q, *p_qf, *p_ckv, *p_kv, *p_attn;
    cudaGetSymbolAddress((void**)&p_h, g_h);
    cudaGetSymbolAddress((void**)&p_qa, g_qa);
    cudaGetSymbolAddress((void**)&p_q, g_q);
    cudaGetSymbolAddress((void**)&p_qf, g_qf);
    cudaGetSymbolAddress((void**)&p_ckv, g_ckv);
    cudaGetSymbolAddress((void**)&p_kv, g_kv);
    cudaGetSymbolAddress((void**)&p_attn, g_attn);

    cudaFuncSetAttribute(flash_attn, cudaFuncAttributeMaxDynamicSharedMemorySize,
                         ATTN_SMEM_BYTES);

    // 1. h = rmsnorm(hidden)
    rmsnorm_k<<<SEQ, 256>>>(hidden, ln_w, p_h, HIDDEN, HIDDEN, HIDDEN);
    // 2. q_a = h @ wq_a^T
    sgemm_nt<<<dim3(QLORA / 128, SEQ / 128), 256>>>(p_h, HIDDEN, wq_a, p_qa,
                                                    SEQ, QLORA, HIDDEN, nullptr, 0.f);
    // 3. q_a = rmsnorm(q_a) (in place)
    rmsnorm_k<<<SEQ, 256>>>(p_qa, q_a_ln, p_qa, QLORA, QLORA, QLORA);
    // 4. q = q_a @ wq_b^T
    sgemm_nt<<<dim3((NHEADS * QKD) / 128, SEQ / 128), 256>>>(p_qa, QLORA, wq_b, p_q,
                                                             SEQ, NHEADS * QKD, QLORA, nullptr, 0.f);
    // 5. ckv = h @ wkv_a^T   (N=576, 5 col-tiles with guard)
    sgemm_nt<<<dim3(5, SEQ / 128), 256>>>(p_h, HIDDEN, wkv_a, p_ckv,
                                          SEQ, KVLORA + ROPE_D, HIDDEN, nullptr, 0.f);
    // 6. rmsnorm first 512 in place (stride 576)
    rmsnorm_k<<<SEQ, 256>>>(p_ckv, kv_a_ln, p_ckv, KVLORA, KVLORA + ROPE_D, KVLORA + ROPE_D);
    // 7. kv = ckv_n @ wkv_b^T
    sgemm_nt<<<dim3((NHEADS * 256) / 128, SEQ / 128), 256>>>(p_ckv, KVLORA + ROPE_D, wkv_b, p_kv,
                                                             SEQ, NHEADS * 256, KVLORA, nullptr, 0.f);
    // 8. rope + scatter Q/K/V (K,V written straight into d_out)
    rope_scatter<<<SEQ, 256>>>(p_q, p_ckv, p_kv, pos, p_qf, k_out, v_out);
    // 9. attention
    flash_attn<<<dim3(SEQ / 64, NHEADS), 256, ATTN_SMEM_BYTES>>>(p_qf, k_out, v_out, p_attn);
    // 10. hidden_out = attn @ wo^T + 0.125 * hidden
    sgemm_nt<<<dim3(HIDDEN / 128, SEQ / 128), 256>>>(p_attn, NHEADS * VDIM, wo, out,
                                                     SEQ, HIDDEN, NHEADS * VDIM,
                                                     hidden, RESID_SCALE);
}

// round 3
// speedup vs baseline: 3.9914x; 3.9914x over previous
#include <cuda_runtime.h>
#include <cuda_bf16.h>
#include <math.h>
#include <stdint.h>

#define HIDDEN 5120
#define NHEADS 16
#define QLORA  1536
#define KVLORA 512
#define NOPE   128
#define ROPE_D 64
#define QKD    192
#define VDIM   128
#define SEQ    2048
#define SM_SCALE 0.07216878364870322f  // 192^-0.5
#define RESID_SCALE 0.125f

// ---------------- scratch ----------------------------------------------------
static __device__ float g_qa[SEQ * QLORA];
static __device__ float g_q[SEQ * NHEADS * QKD];
static __device__ float g_ckv[SEQ * 576];
static __device__ float g_kv[SEQ * 4096];

static __device__ __nv_bfloat16 g_h_hi[SEQ * HIDDEN],    g_h_lo[SEQ * HIDDEN];
static __device__ __nv_bfloat16 g_qa_hi[SEQ * QLORA],    g_qa_lo[SEQ * QLORA];
static __device__ __nv_bfloat16 g_ckvn_hi[SEQ * KVLORA], g_ckvn_lo[SEQ * KVLORA];
static __device__ __nv_bfloat16 g_attn_hi[SEQ * 2048],   g_attn_lo[SEQ * 2048];
static __device__ __nv_bfloat16 g_qf_hi[NHEADS * SEQ * QKD], g_qf_lo[NHEADS * SEQ * QKD];
static __device__ __nv_bfloat16 g_k_hi[NHEADS * SEQ * QKD],  g_k_lo[NHEADS * SEQ * QKD];
static __device__ __nv_bfloat16 g_v_hi[NHEADS * SEQ * VDIM], g_v_lo[NHEADS * SEQ * VDIM];

static __device__ __nv_bfloat16 g_wqa_hi[QLORA * HIDDEN],  g_wqa_lo[QLORA * HIDDEN];
static __device__ __nv_bfloat16 g_wqb_hi[3072 * QLORA],    g_wqb_lo[3072 * QLORA];
static __device__ __nv_bfloat16 g_wkva_hi[576 * HIDDEN],   g_wkva_lo[576 * HIDDEN];
static __device__ __nv_bfloat16 g_wkvb_hi[4096 * KVLORA],  g_wkvb_lo[4096 * KVLORA];
static __device__ __nv_bfloat16 g_wo_hi[HIDDEN * 2048],    g_wo_lo[HIDDEN * 2048];

// ---------------- helpers ----------------------------------------------------
__device__ __forceinline__ uint32_t smem_u32(const void* p) {
    return (uint32_t)__cvta_generic_to_shared(p);
}
__device__ __forceinline__ void cpa16(uint32_t dst, const void* src, int sz) {
    asm volatile("cp.async.cg.shared.global [%0], [%1], 16, %2;"
                 :: "r"(dst), "l"(src), "r"(sz) : "memory");
}
#define CP_COMMIT() asm volatile("cp.async.commit_group;" ::: "memory")
#define CP_WAIT(n)  asm volatile("cp.async.wait_group %0;" :: "n"(n) : "memory")

__device__ __forceinline__ void ldsm4(uint32_t& r0, uint32_t& r1, uint32_t& r2, uint32_t& r3,
                                      uint32_t addr) {
    asm volatile("ldmatrix.sync.aligned.m8n8.x4.shared.b16 {%0,%1,%2,%3}, [%4];"
                 : "=r"(r0), "=r"(r1), "=r"(r2), "=r"(r3) : "r"(addr));
}
__device__ __forceinline__ void ldsm4t(uint32_t& r0, uint32_t& r1, uint32_t& r2, uint32_t& r3,
                                       uint32_t addr) {
    asm volatile("ldmatrix.sync.aligned.m8n8.x4.trans.shared.b16 {%0,%1,%2,%3}, [%4];"
                 : "=r"(r0), "=r"(r1), "=r"(r2), "=r"(r3) : "r"(addr));
}
__device__ __forceinline__ void mma16816(float* c, uint32_t a0, uint32_t a1, uint32_t a2,
                                         uint32_t a3, uint32_t b0, uint32_t b1) {
    asm volatile(
        "mma.sync.aligned.m16n8k16.row.col.f32.bf16.bf16.f32 "
        "{%0,%1,%2,%3}, {%4,%5,%6,%7}, {%8,%9}, {%0,%1,%2,%3};"
        : "+f"(c[0]), "+f"(c[1]), "+f"(c[2]), "+f"(c[3])
        : "r"(a0), "r"(a1), "r"(a2), "r"(a3), "r"(b0), "r"(b1));
}
__device__ __forceinline__ uint32_t bpack(float a, float b) {
    __nv_bfloat162 t = __floats2bfloat162_rn(a, b);
    return *reinterpret_cast<uint32_t*>(&t);
}
__device__ __forceinline__ void split2(float v0, float v1, uint32_t& hi, uint32_t& lo) {
    __nv_bfloat16 h0 = __float2bfloat16(v0), h1 = __float2bfloat16(v1);
    float r0 = v0 - __bfloat162float(h0), r1 = v1 - __bfloat162float(h1);
    hi = bpack(__bfloat162float(h0), __bfloat162float(h1));  // exact re-pack
    lo = bpack(r0, r1);
    (void)hi;
    __nv_bfloat162 th; th.x = h0; th.y = h1;
    hi = *reinterpret_cast<uint32_t*>(&th);
}

// ---------------- fp32 -> bf16 hi/lo converters -------------------------------
__global__ void cvt_b16(const float* __restrict__ x, __nv_bfloat16* __restrict__ hi,
                        __nv_bfloat16* __restrict__ lo, long n)
{
    for (long i = (long)blockIdx.x * blockDim.x + threadIdx.x; i < n;
         i += (long)gridDim.x * blockDim.x) {
        float v = x[i];
        __nv_bfloat16 h = __float2bfloat16(v);
        hi[i] = h;
        lo[i] = __float2bfloat16(v - __bfloat162float(h));
    }
}

__global__ void rmsnorm_b16(const float* __restrict__ x, const float* __restrict__ w,
                            __nv_bfloat16* __restrict__ hi, __nv_bfloat16* __restrict__ lo,
                            int cols, int strideIn, int strideOut)
{
    int row = blockIdx.x;
    int t = threadIdx.x;
    const float* xr = x + (long)row * strideIn;
    float ss = 0.f;
    for (int c = t; c < cols; c += 256) { float v = xr[c]; ss = fmaf(v, v, ss); }
    __shared__ float red[256];
    red[t] = ss; __syncthreads();
    for (int s = 128; s > 0; s >>= 1) { if (t < s) red[t] += red[t + s]; __syncthreads(); }
    float scale = rsqrtf(red[0] / (float)cols + 1e-6f);
    __nv_bfloat16* hr = hi + (long)row * strideOut;
    __nv_bfloat16* lr = lo + (long)row * strideOut;
    for (int c = t; c < cols; c += 256) {
        float v = xr[c] * scale * w[c];
        __nv_bfloat16 h = __float2bfloat16(v);
        hr[c] = h;
        lr[c] = __float2bfloat16(v - __bfloat162float(h));
    }
}

// ---------------- mma.sync bf16x3 GEMM: C = A*B^T (+beta*D) -------------------
// CTA tile 128x128, Kc=32, 256 threads (8 warps, 2x4), warp tile 64x32.
#define GPADB 80            // bytes per smem row (32 bf16 + 8 pad)
#define GT_BYTES (128 * GPADB)      // 10240
#define GS_BYTES (4 * GT_BYTES)     // 40960 per stage
#define GEMM_SMEM (2 * GS_BYTES)    // 81920

__device__ __forceinline__ void g_fill(uint32_t dstBase, const __nv_bfloat16* __restrict__ src,
                                       long ld, int rmax, int t)
{
#pragma unroll
    for (int i = 0; i < 2; ++i) {
        int id = t + 256 * i;          // 0..511
        int row = id >> 2, ch = id & 3;
        bool ok = row < rmax;
        const __nv_bfloat16* g = src + (long)(ok ? row : 0) * ld + ch * 8;
        cpa16(dstBase + row * GPADB + ch * 16, g, ok ? 16 : 0);
    }
}

__global__ __launch_bounds__(256, 1)
void gemm_mma(const __nv_bfloat16* __restrict__ Ah, const __nv_bfloat16* __restrict__ Al, int lda,
              const __nv_bfloat16* __restrict__ Bh, const __nv_bfloat16* __restrict__ Bl,
              float* __restrict__ C, int M, int N, int K,
              const float* __restrict__ D, float beta)
{
    extern __shared__ __align__(128) char smem[];
    uint32_t sb = smem_u32(smem);
    int t = threadIdx.x;
    int warp = t >> 5, lane = t & 31;
    int wm = warp >> 2, wn = warp & 3;
    int n0 = blockIdx.x * 128, m0 = blockIdx.y * 128;
    int nc = K / 32;

    float acc[4][4][4];
#pragma unroll
    for (int i = 0; i < 4; i++)
#pragma unroll
        for (int j = 0; j < 4; j++)
#pragma unroll
            for (int r = 0; r < 4; r++) acc[i][j][r] = 0.f;

    // prologue: load chunk 0 into stage 0
    {
        uint32_t b0 = sb;
        g_fill(b0 + 0 * GT_BYTES, Ah + (long)m0 * lda, lda, M - m0, t);
        g_fill(b0 + 1 * GT_BYTES, Al + (long)m0 * lda, lda, M - m0, t);
        g_fill(b0 + 2 * GT_BYTES, Bh + (long)n0 * K, K, N - n0, t);
        g_fill(b0 + 3 * GT_BYTES, Bl + (long)n0 * K, K, N - n0, t);
        CP_COMMIT();
    }

    uint32_t aoff = (uint32_t)((wm * 64 + (lane & 15)) * GPADB + (lane >> 4) * 16);
    uint32_t boff = (uint32_t)(2 * GT_BYTES +
                               (wn * 32 + (lane & 7) + ((lane >> 4) << 3)) * GPADB +
                               ((lane >> 3) & 1) * 16);

    for (int c = 0; c < nc; ++c) {
        if (c + 1 < nc) {
            uint32_t bn = sb + ((c + 1) & 1) * GS_BYTES;
            int kc0 = (c + 1) * 32;
            g_fill(bn + 0 * GT_BYTES, Ah + (long)m0 * lda + kc0, lda, M - m0, t);
            g_fill(bn + 1 * GT_BYTES, Al + (long)m0 * lda + kc0, lda, M - m0, t);
            g_fill(bn + 2 * GT_BYTES, Bh + (long)n0 * K + kc0, K, N - n0, t);
            g_fill(bn + 3 * GT_BYTES, Bl + (long)n0 * K + kc0, K, N - n0, t);
            CP_COMMIT();
            CP_WAIT(1);
        } else {
            CP_WAIT(0);
        }
        __syncthreads();
        uint32_t base = sb + (c & 1) * GS_BYTES;

#pragma unroll
        for (int k16 = 0; k16 < 2; ++k16) {
            uint32_t ah[4][4], al_[4][4];
#pragma unroll
            for (int im = 0; im < 4; ++im) {
                uint32_t addr = base + aoff + im * 16 * GPADB + k16 * 32;
                ldsm4(ah[im][0], ah[im][1], ah[im][2], ah[im][3], addr);
                ldsm4(al_[im][0], al_[im][1], al_[im][2], al_[im][3], addr + GT_BYTES);
            }
            uint32_t bh[4][2], bl[4][2];
#pragma unroll
            for (int j2 = 0; j2 < 2; ++j2) {
                uint32_t addr = base + boff + j2 * 16 * GPADB + k16 * 32;
                uint32_t r0, r1, r2, r3;
                ldsm4(r0, r1, r2, r3, addr);
                bh[2 * j2][0] = r0; bh[2 * j2][1] = r1;
                bh[2 * j2 + 1][0] = r2; bh[2 * j2 + 1][1] = r3;
                ldsm4(r0, r1, r2, r3, addr + GT_BYTES);
                bl[2 * j2][0] = r0; bl[2 * j2][1] = r1;
                bl[2 * j2 + 1][0] = r2; bl[2 * j2 + 1][1] = r3;
            }
#pragma unroll
            for (int im = 0; im < 4; ++im)
#pragma unroll
                for (int jn = 0; jn < 4; ++jn) {
                    mma16816(acc[im][jn], ah[im][0], ah[im][1], ah[im][2], ah[im][3],
                             bh[jn][0], bh[jn][1]);
                    mma16816(acc[im][jn], ah[im][0], ah[im][1], ah[im][2], ah[im][3],
                             bl[jn][0], bl[jn][1]);
                    mma16816(acc[im][jn], al_[im][0], al_[im][1], al_[im][2], al_[im][3],
                             bh[jn][0], bh[jn][1]);
                }
        }
        __syncthreads();
    }

    // epilogue
#pragma unroll
    for (int im = 0; im < 4; ++im) {
        int row0 = m0 + wm * 64 + im * 16 + (lane >> 2);
#pragma unroll
        for (int jn = 0; jn < 4; ++jn) {
            int col = n0 + wn * 32 + jn * 8 + (lane & 3) * 2;
            if (col < N) {
                float2 v0 = make_float2(acc[im][jn][0], acc[im][jn][1]);
                float2 v1 = make_float2(acc[im][jn][2], acc[im][jn][3]);
                if (D) {
                    float2 d0 = *(const float2*)&D[(long)row0 * N + col];
                    float2 d1 = *(const float2*)&D[(long)(row0 + 8) * N + col];
                    v0.x = fmaf(beta, d0.x, v0.x); v0.y = fmaf(beta, d0.y, v0.y);
                    v1.x = fmaf(beta, d1.x, v1.x); v1.y = fmaf(beta, d1.y, v1.y);
                }
                *(float2*)&C[(long)row0 * N + col] = v0;
                *(float2*)&C[(long)(row0 + 8) * N + col] = v1;
            }
        }
    }
}

// ---------------- RoPE + scatter (fp32 K/V out + bf16 hi/lo Q/K/V) ------------
__global__ void rope_scatter(const float* __restrict__ qin,  // [s][3072]
                             const float* __restrict__ ckv,  // [s][576]
                             const float* __restrict__ kvin, // [s][4096]
                             const int* __restrict__ pos_ids,
                             __nv_bfloat16* __restrict__ qh, __nv_bfloat16* __restrict__ ql,
                             float* __restrict__ kout,
                             __nv_bfloat16* __restrict__ kh, __nv_bfloat16* __restrict__ kl,
                             float* __restrict__ vout,
                             __nv_bfloat16* __restrict__ vh, __nv_bfloat16* __restrict__ vl)
{
    int s = blockIdx.x;
    int t = threadIdx.x;
    __shared__ float cs[32], sn[32], kr[64];
    if (t < 32) {
        double invf = exp(-(double)t * 0.28782313662425575); // ln(10000)/32
        double ang = (double)pos_ids[s] * invf;
        cs[t] = (float)cos(ang);
        sn[t] = (float)sin(ang);
    }
    __syncthreads();
    if (t < 32) {
        float x0 = ckv[s * 576 + 512 + 2 * t];
        float x1 = ckv[s * 576 + 512 + 2 * t + 1];
        kr[t]      = x0 * cs[t] - x1 * sn[t];
        kr[32 + t] = x1 * cs[t] + x0 * sn[t];
    }
    __syncthreads();
    // Q rope part
    for (int idx = t; idx < 512; idx += 256) {
        int h = idx >> 5, j = idx & 31;
        const float* qb = qin + (long)s * 3072 + h * 192;
        float x0 = qb[128 + 2 * j], x1 = qb[128 + 2 * j + 1];
        float a = x0 * cs[j] - x1 * sn[j];
        float b = x1 * cs[j] + x0 * sn[j];
        long o = ((long)h * SEQ + s) * 192;
        __nv_bfloat16 ha = __float2bfloat16(a), hb = __float2bfloat16(b);
        qh[o + 128 + j] = ha; ql[o + 128 + j] = __float2bfloat16(a - __bfloat162float(ha));
        qh[o + 160 + j] = hb; ql[o + 160 + j] = __float2bfloat16(b - __bfloat162float(hb));
    }
    // Q nope
    for (int idx = t; idx < 2048; idx += 256) {
        int h = idx >> 7, d = idx & 127;
        float v = qin[(long)s * 3072 + h * 192 + d];
        long o = ((long)h * SEQ + s) * 192 + d;
        __nv_bfloat16 hv = __float2bfloat16(v);
        qh[o] = hv; ql[o] = __float2bfloat16(v - __bfloat162float(hv));
    }
    // K
    for (int idx = t; idx < 16 * 192; idx += 256) {
        int h = idx / 192, d = idx - h * 192;
        float v = (d < 128) ? kvin[(long)s * 4096 + h * 256 + d] : kr[d - 128];
        long o = ((long)h * SEQ + s) * 192 + d;
        kout[o] = v;
        __nv_bfloat16 hv = __float2bfloat16(v);
        kh[o] = hv; kl[o] = __float2bfloat16(v - __bfloat162float(hv));
    }
    // V
    for (int idx = t; idx < 2048; idx += 256) {
        int h = idx >> 7, d = idx & 127;
        float v = kvin[(long)s * 4096 + h * 256 + 128 + d];
        long o = ((long)h * SEQ + s) * 128 + d;
        vout[o] = v;
        __nv_bfloat16 hv = __float2bfloat16(v);
        vh[o] = hv; vl[o] = __float2bfloat16(v - __bfloat162float(hv));
    }
}

// ---------------- flash attention, mma.sync bf16x3 ----------------------------
// Q tile 64 rows, 4 warps (16 rows each, full 64-key width), K tiles of 64.
#define FPADB 400   // (192+8)*2 bytes per smem row for Q/K
#define VPADB 272   // (128+8)*2 bytes per smem row for V
#define SQH 0
#define SQL (SQH + 64 * FPADB)
#define SKH (SQL + 64 * FPADB)
#define SKL (SKH + 64 * FPADB)
#define SVH (SKL + 64 * FPADB)
#define SVL (SVH + 64 * VPADB)
#define FLASH_SMEM (SVL + 64 * VPADB)   // 137216 B

__global__ __launch_bounds__(128, 1)
void flash_mma(const __nv_bfloat16* __restrict__ Qh_g, const __nv_bfloat16* __restrict__ Ql_g,
               const __nv_bfloat16* __restrict__ Kh_g, const __nv_bfloat16* __restrict__ Kl_g,
               const __nv_bfloat16* __restrict__ Vh_g, const __nv_bfloat16* __restrict__ Vl_g,
               __nv_bfloat16* __restrict__ Oh_g, __nv_bfloat16* __restrict__ Ol_g)
{
    extern __shared__ __align__(128) char smem[];
    uint32_t sb = smem_u32(smem);
    int qt = blockIdx.x, h = blockIdx.y;
    int q0 = qt * 64;
    int t = threadIdx.x;
    int warp = t >> 5, lane = t & 31;

    // load Q tile (hi + lo): 64 x 192 bf16 each = 1536 16B-chunks each
    {
        const __nv_bfloat16* qg = Qh_g + ((long)h * SEQ + q0) * 192;
        const __nv_bfloat16* qg2 = Ql_g + ((long)h * SEQ + q0) * 192;
#pragma unroll
        for (int i = 0; i < 12; ++i) {
            int id = t + 128 * i;
            int row = id / 24, ch = id % 24;
            cpa16(sb + SQH + row * FPADB + ch * 16, qg + row * 192 + ch * 8, 16);
            cpa16(sb + SQL + row * FPADB + ch * 16, qg2 + row * 192 + ch * 8, 16);
        }
        CP_COMMIT();
    }

    float o[16][4];
#pragma unroll
    for (int i = 0; i < 16; i++)
#pragma unroll
        for (int r = 0; r < 4; r++) o[i][r] = 0.f;
    float mrow[2] = {-1e30f, -1e30f};
    float lrow[2] = {0.f, 0.f};

    uint32_t qoff = (uint32_t)(SQH + (warp * 16 + (lane & 15)) * FPADB + (lane >> 4) * 16);
    uint32_t koff = (uint32_t)(SKH + ((lane & 7) + ((lane >> 4) << 3)) * FPADB +
                               ((lane >> 3) & 1) * 16);
    uint32_t voff = (uint32_t)(SVH + ((lane & 7) + (((lane >> 3) & 1) << 3)) * VPADB +
                               ((lane >> 4) << 3) * 2);

    int rA = (lane >> 2);               // local row within warp-16 block
    int colq = (lane & 3) * 2;

    const __nv_bfloat16* Kgh = Kh_g + (long)h * SEQ * 192;
    const __nv_bfloat16* Kgl = Kl_g + (long)h * SEQ * 192;
    const __nv_bfloat16* Vgh = Vh_g + (long)h * SEQ * 128;
    const __nv_bfloat16* Vgl = Vl_g + (long)h * SEQ * 128;

    for (int kt = 0; kt <= qt; ++kt) {
        int k0 = kt * 64;
        if (kt > 0) __syncthreads();
        // load K (hi/lo) + V (hi/lo)
#pragma unroll
        for (int i = 0; i < 12; ++i) {
            int id = t + 128 * i;
            int row = id / 24, ch = id % 24;
            cpa16(sb + SKH + row * FPADB + ch * 16, Kgh + (long)(k0 + row) * 192 + ch * 8, 16);
            cpa16(sb + SKL + row * FPADB + ch * 16, Kgl + (long)(k0 + row) * 192 + ch * 8, 16);
        }
#pragma unroll
        for (int i = 0; i < 8; ++i) {
            int id = t + 128 * i;
            int row = id >> 4, ch = id & 15;
            cpa16(sb + SVH + row * VPADB + ch * 16, Vgh + (long)(k0 + row) * 128 + ch * 8, 16);
            cpa16(sb + SVL + row * VPADB + ch * 16, Vgl + (long)(k0 + row) * 128 + ch * 8, 16);
        }
        CP_COMMIT();
        CP_WAIT(0);
        __syncthreads();

        // ---- S = Q @ K^T (m16 x n64, k=192) ----
        float sc[8][4];
#pragma unroll
        for (int j = 0; j < 8; j++)
#pragma unroll
            for (int r = 0; r < 4; r++) sc[j][r] = 0.f;

#pragma unroll 1
        for (int k16 = 0; k16 < 12; ++k16) {
            uint32_t qfh[4], qfl[4];
            uint32_t addr = sb + qoff + k16 * 32;
            ldsm4(qfh[0], qfh[1], qfh[2], qfh[3], addr);
            ldsm4(qfl[0], qfl[1], qfl[2], qfl[3], addr + (SQL - SQH));
            uint32_t kbh[8][2], kbl[8][2];
#pragma unroll
            for (int j2 = 0; j2 < 4; ++j2) {
                uint32_t ka = sb + koff + j2 * 16 * FPADB + k16 * 32;
                uint32_t r0, r1, r2, r3;
                ldsm4(r0, r1, r2, r3, ka);
                kbh[2 * j2][0] = r0; kbh[2 * j2][1] = r1;
                kbh[2 * j2 + 1][0] = r2; kbh[2 * j2 + 1][1] = r3;
                ldsm4(r0, r1, r2, r3, ka + (SKL - SKH));
                kbl[2 * j2][0] = r0; kbl[2 * j2][1] = r1;
                kbl[2 * j2 + 1][0] = r2; kbl[2 * j2 + 1][1] = r3;
            }
#pragma unroll
            for (int j = 0; j < 8; ++j) {
                mma16816(sc[j], qfh[0], qfh[1], qfh[2], qfh[3], kbh[j][0], kbh[j][1]);
                mma16816(sc[j], qfh[0], qfh[1], qfh[2], qfh[3], kbl[j][0], kbl[j][1]);
                mma16816(sc[j], qfl[0], qfl[1], qfl[2], qfl[3], kbh[j][0], kbh[j][1]);
            }
        }

        int rowA = q0 + warp * 16 + rA;
        int rowB = rowA + 8;
#pragma unroll
        for (int j = 0; j < 8; ++j) {
#pragma unroll
            for (int r = 0; r < 4; r++) sc[j][r] *= SM_SCALE;
            if (kt == qt) {
                int col = k0 + j * 8 + colq;
                if (col > rowA)     sc[j][0] = -1e30f;
                if (col + 1 > rowA) sc[j][1] = -1e30f;
                if (col > rowB)     sc[j][2] = -1e30f;
                if (col + 1 > rowB) sc[j][3] = -1e30f;
            }
        }
        // row max (rows rA, rA+8)
        float mxa = -1e30f, mxb = -1e30f;
#pragma unroll
        for (int j = 0; j < 8; ++j) {
            mxa = fmaxf(mxa, fmaxf(sc[j][0], sc[j][1]));
            mxb = fmaxf(mxb, fmaxf(sc[j][2], sc[j][3]));
        }
        mxa = fmaxf(mxa, __shfl_xor_sync(0xffffffffu, mxa, 1));
        mxa = fmaxf(mxa, __shfl_xor_sync(0xffffffffu, mxa, 2));
        mxb = fmaxf(mxb, __shfl_xor_sync(0xffffffffu, mxb, 1));
        mxb = fmaxf(mxb, __shfl_xor_sync(0xffffffffu, mxb, 2));
        float mna = fmaxf(mrow[0], mxa), mnb = fmaxf(mrow[1], mxb);
        float ala = __expf(mrow[0] - mna), alb = __expf(mrow[1] - mnb);
        mrow[0] = mna; mrow[1] = mnb;

        float suma = 0.f, sumb = 0.f;
#pragma unroll
        for (int j = 0; j < 8; ++j) {
            sc[j][0] = __expf(sc[j][0] - mna);
            sc[j][1] = __expf(sc[j][1] - mna);
            sc[j][2] = __expf(sc[j][2] - mnb);
            sc[j][3] = __expf(sc[j][3] - mnb);
            suma += sc[j][0] + sc[j][1];
            sumb += sc[j][2] + sc[j][3];
        }
        suma += __shfl_xor_sync(0xffffffffu, suma, 1);
        suma += __shfl_xor_sync(0xffffffffu, suma, 2);
        sumb += __shfl_xor_sync(0xffffffffu, sumb, 1);
        sumb += __shfl_xor_sync(0xffffffffu, sumb, 2);
        lrow[0] = lrow[0] * ala + suma;
        lrow[1] = lrow[1] * alb + sumb;
#pragma unroll
        for (int nb = 0; nb < 16; ++nb) {
            o[nb][0] *= ala; o[nb][1] *= ala;
            o[nb][2] *= alb; o[nb][3] *= alb;
        }

        // pack P into A-frags (hi + lo)
        uint32_t pah[4][4], pal[4][4];
#pragma unroll
        for (int j = 0; j < 4; ++j) {
            split2(sc[2 * j][0],     sc[2 * j][1],     pah[j][0], pal[j][0]);
            split2(sc[2 * j][2],     sc[2 * j][3],     pah[j][1], pal[j][1]);
            split2(sc[2 * j + 1][0], sc[2 * j + 1][1], pah[j][2], pal[j][2]);
            split2(sc[2 * j + 1][2], sc[2 * j + 1][3], pah[j][3], pal[j][3]);
        }

        // ---- O += P @ V ----
#pragma unroll 1
        for (int j = 0; j < 4; ++j) {
            uint32_t vbase = sb + voff + (j * 16 + 0) * VPADB;  // kk base handled in voff
            // voff encodes (lane&7) + ((lane>>3)&1)*8 row; add j*16 rows:
#pragma unroll
            for (int nb2 = 0; nb2 < 8; ++nb2) {
                uint32_t va = sb + voff + j * 16 * VPADB + nb2 * 32;  // 16 cols * 2B
                uint32_t h0, h1, h2, h3, l0, l1, l2, l3;
                ldsm4t(h0, h1, h2, h3, va);
                ldsm4t(l0, l1, l2, l3, va + (SVL - SVH));
                mma16816(o[2 * nb2],     pah[j][0], pah[j][1], pah[j][2], pah[j][3], h0, h1);
                mma16816(o[2 * nb2],     pah[j][0], pah[j][1], pah[j][2], pah[j][3], l0, l1);
                mma16816(o[2 * nb2],     pal[j][0], pal[j][1], pal[j][2], pal[j][3], h0, h1);
                mma16816(o[2 * nb2 + 1], pah[j][0], pah[j][1], pah[j][2], pah[j][3], h2, h3);
                mma16816(o[2 * nb2 + 1], pah[j][0], pah[j][1], pah[j][2], pah[j][3], l2, l3);
                mma16816(o[2 * nb2 + 1], pal[j][0], pal[j][1], pal[j][2], pal[j][3], h2, h3);
            }
            (void)vbase;
        }
    }

    // epilogue: normalize and store bf16 hi/lo into [s][2048]
    float inva = 1.0f / lrow[0], invb = 1.0f / lrow[1];
    int rowA = q0 + warp * 16 + rA;
    int rowB = rowA + 8;
#pragma unroll
    for (int nb = 0; nb < 16; ++nb) {
        int col = h * 128 + nb * 8 + colq;
        uint32_t hA, lA, hB, lB;
        split2(o[nb][0] * inva, o[nb][1] * inva, hA, lA);
        split2(o[nb][2] * invb, o[nb][3] * invb, hB, lB);
        *(uint32_t*)&Oh_g[(long)rowA * 2048 + col] = hA;
        *(uint32_t*)&Ol_g[(long)rowA * 2048 + col] = lA;
        *(uint32_t*)&Oh_g[(long)rowB * 2048 + col] = hB;
        *(uint32_t*)&Ol_g[(long)rowB * 2048 + col] = lB;
    }
}

// ---------------- launch ------------------------------------------------------
extern "C" void kernel_launch(void* const* d_in, const int* in_sizes, int n_in,
                              void* d_out, int out_size)
{
    const float* hidden   = (const float*)d_in[0];
    const int*   pos      = (const int*)d_in[1];
    const float* ln_w     = (const float*)d_in[3];
    const float* wq_a     = (const float*)d_in[4];
    const float* q_a_ln   = (const float*)d_in[5];
    const float* wq_b     = (const float*)d_in[6];
    const float* wkv_a    = (const float*)d_in[7];
    const float* kv_a_ln  = (const float*)d_in[8];
    const float* wkv_b    = (const float*)d_in[9];
    const float* wo       = (const float*)d_in[10];

    float* out   = (float*)d_out;
    float* k_out = out + (long)SEQ * HIDDEN;
    float* v_out = k_out + (long)NHEADS * SEQ * QKD;

    float *p_qa, *p_q, *p_ckv, *p_kv;
    cudaGetSymbolAddress((void**)&p_qa, g_qa);
    cudaGetSymbolAddress((void**)&p_q, g_q);
    cudaGetSymbolAddress((void**)&p_ckv, g_ckv);
    cudaGetSymbolAddress((void**)&p_kv, g_kv);

    __nv_bfloat16 *h_hi, *h_lo, *qa_hi, *qa_lo, *ckvn_hi, *ckvn_lo, *attn_hi, *attn_lo;
    __nv_bfloat16 *qf_hi, *qf_lo, *k_hi, *k_lo, *v_hi, *v_lo;
    __nv_bfloat16 *wqa_hi, *wqa_lo, *wqb_hi, *wqb_lo, *wkva_hi, *wkva_lo, *wkvb_hi, *wkvb_lo, *wo_hi, *wo_lo;
    cudaGetSymbolAddress((void**)&h_hi, g_h_hi);       cudaGetSymbolAddress((void**)&h_lo, g_h_lo);
    cudaGetSymbolAddress((void**)&qa_hi, g_qa_hi);     cudaGetSymbolAddress((void**)&qa_lo, g_qa_lo);
    cudaGetSymbolAddress((void**)&ckvn_hi, g_ckvn_hi); cudaGetSymbolAddress((void**)&ckvn_lo, g_ckvn_lo);
    cudaGetSymbolAddress((void**)&attn_hi, g_attn_hi); cudaGetSymbolAddress((void**)&attn_lo, g_attn_lo);
    cudaGetSymbolAddress((void**)&qf_hi, g_qf_hi);     cudaGetSymbolAddress((void**)&qf_lo, g_qf_lo);
    cudaGetSymbolAddress((void**)&k_hi, g_k_hi);       cudaGetSymbolAddress((void**)&k_lo, g_k_lo);
    cudaGetSymbolAddress((void**)&v_hi, g_v_hi);       cudaGetSymbolAddress((void**)&v_lo, g_v_lo);
    cudaGetSymbolAddress((void**)&wqa_hi, g_wqa_hi);   cudaGetSymbolAddress((void**)&wqa_lo, g_wqa_lo);
    cudaGetSymbolAddress((void**)&wqb_hi, g_wqb_hi);   cudaGetSymbolAddress((void**)&wqb_lo, g_wqb_lo);
    cudaGetSymbolAddress((void**)&wkva_hi, g_wkva_hi); cudaGetSymbolAddress((void**)&wkva_lo, g_wkva_lo);
    cudaGetSymbolAddress((void**)&wkvb_hi, g_wkvb_hi); cudaGetSymbolAddress((void**)&wkvb_lo, g_wkvb_lo);
    cudaGetSymbolAddress((void**)&wo_hi, g_wo_hi);     cudaGetSymbolAddress((void**)&wo_lo, g_wo_lo);

    cudaFuncSetAttribute(gemm_mma, cudaFuncAttributeMaxDynamicSharedMemorySize, GEMM_SMEM);
    cudaFuncSetAttribute(flash_mma, cudaFuncAttributeMaxDynamicSharedMemorySize, FLASH_SMEM);

    // weight conversions
    cvt_b16<<<592, 256>>>(wq_a,  wqa_hi,  wqa_lo,  (long)QLORA * HIDDEN);
    cvt_b16<<<592, 256>>>(wq_b,  wqb_hi,  wqb_lo,  (long)3072 * QLORA);
    cvt_b16<<<592, 256>>>(wkv_a, wkva_hi, wkva_lo, (long)576 * HIDDEN);
    cvt_b16<<<592, 256>>>(wkv_b, wkvb_hi, wkvb_lo, (long)4096 * KVLORA);
    cvt_b16<<<592, 256>>>(wo,    wo_hi,   wo_lo,   (long)HIDDEN * 2048);

    // 1. h = rmsnorm(hidden) -> bf16 hi/lo
    rmsnorm_b16<<<SEQ, 256>>>(hidden, ln_w, h_hi, h_lo, HIDDEN, HIDDEN, HIDDEN);
    // 2. q_a = h @ wq_a^T
    gemm_mma<<<dim3(QLORA / 128, SEQ / 128), 256, GEMM_SMEM>>>(
        h_hi, h_lo, HIDDEN, wqa_hi, wqa_lo, p_qa, SEQ, QLORA, HIDDEN, nullptr, 0.f);
    // 3. rmsnorm(q_a)
    rmsnorm_b16<<<SEQ, 256>>>(p_qa, q_a_ln, qa_hi, qa_lo, QLORA, QLORA, QLORA);
    // 4. q = qa_n @ wq_b^T
    gemm_mma<<<dim3(3072 / 128, SEQ / 128), 256, GEMM_SMEM>>>(
        qa_hi, qa_lo, QLORA, wqb_hi, wqb_lo, p_q, SEQ, 3072, QLORA, nullptr, 0.f);
    // 5. ckv = h @ wkv_a^T
    gemm_mma<<<dim3(5, SEQ / 128), 256, GEMM_SMEM>>>(
        h_hi, h_lo, HIDDEN, wkva_hi, wkva_lo, p_ckv, SEQ, 576, HIDDEN, nullptr, 0.f);
    // 6. rmsnorm(ckv[:, :512])
    rmsnorm_b16<<<SEQ, 256>>>(p_ckv, kv_a_ln, ckvn_hi, ckvn_lo, KVLORA, 576, KVLORA);
    // 7. kv = ckv_n @ wkv_b^T
    gemm_mma<<<dim3(4096 / 128, SEQ / 128), 256, GEMM_SMEM>>>(
        ckvn_hi, ckvn_lo, KVLORA, wkvb_hi, wkvb_lo, p_kv, SEQ, 4096, KVLORA, nullptr, 0.f);
    // 8. rope + scatter
    rope_scatter<<<SEQ, 256>>>(p_q, p_ckv, p_kv, pos, qf_hi, qf_lo,
                               k_out, k_hi, k_lo, v_out, v_hi, v_lo);
    // 9. attention
    flash_mma<<<dim3(SEQ / 64, NHEADS), 128, FLASH_SMEM>>>(
        qf_hi, qf_lo, k_hi, k_lo, v_hi, v_lo, attn_hi, attn_lo);
    // 10. out = attn @ wo^T + 0.125 * hidden
    gemm_mma<<<dim3(HIDDEN / 128, SEQ / 128), 256, GEMM_SMEM>>>(
        attn_hi, attn_lo, 2048, wo_hi, wo_lo, out, SEQ, HIDDEN, 2048,
        hidden, RESID_SCALE);
}

// round 4
// speedup vs baseline: 4.1769x; 1.0465x over previous
#include <cuda_runtime.h>
#include <cuda_bf16.h>
#include <math.h>
#include <stdint.h>

#define HIDDEN 5120
#define NHEADS 16
#define QLORA  1536
#define KVLORA 512
#define NOPE   128
#define ROPE_D 64
#define QKD    192
#define VDIM   128
#define SEQ    2048
#define SM_SCALE 0.07216878364870322f  // 192^-0.5
#define RESID_SCALE 0.125f

// ---------------- scratch ----------------------------------------------------
static __device__ float g_qa[SEQ * QLORA];
static __device__ float g_q[SEQ * NHEADS * QKD];
static __device__ float g_ckv[SEQ * 576];
static __device__ float g_kv[SEQ * 4096];

static __device__ __nv_bfloat16 g_h_hi[SEQ * HIDDEN],    g_h_lo[SEQ * HIDDEN];
static __device__ __nv_bfloat16 g_qa_hi[SEQ * QLORA],    g_qa_lo[SEQ * QLORA];
static __device__ __nv_bfloat16 g_ckvn_hi[SEQ * KVLORA], g_ckvn_lo[SEQ * KVLORA];
static __device__ __nv_bfloat16 g_attn_hi[SEQ * 2048],   g_attn_lo[SEQ * 2048];
static __device__ __nv_bfloat16 g_qf_hi[NHEADS * SEQ * QKD], g_qf_lo[NHEADS * SEQ * QKD];
static __device__ __nv_bfloat16 g_k_hi[NHEADS * SEQ * QKD],  g_k_lo[NHEADS * SEQ * QKD];
static __device__ __nv_bfloat16 g_v_hi[NHEADS * SEQ * VDIM], g_v_lo[NHEADS * SEQ * VDIM];

static __device__ __nv_bfloat16 g_wqa_hi[QLORA * HIDDEN],  g_wqa_lo[QLORA * HIDDEN];
static __device__ __nv_bfloat16 g_wqb_hi[3072 * QLORA],    g_wqb_lo[3072 * QLORA];
static __device__ __nv_bfloat16 g_wkva_hi[576 * HIDDEN],   g_wkva_lo[576 * HIDDEN];
static __device__ __nv_bfloat16 g_wkvb_hi[4096 * KVLORA],  g_wkvb_lo[4096 * KVLORA];
static __device__ __nv_bfloat16 g_wo_hi[HIDDEN * 2048],    g_wo_lo[HIDDEN * 2048];

// ---------------- helpers ----------------------------------------------------
__device__ __forceinline__ uint32_t smem_u32(const void* p) {
    return (uint32_t)__cvta_generic_to_shared(p);
}
__device__ __forceinline__ void cpa16(uint32_t dst, const void* src, int sz) {
    asm volatile("cp.async.cg.shared.global [%0], [%1], 16, %2;"
                 :: "r"(dst), "l"(src), "r"(sz) : "memory");
}
#define CP_COMMIT() asm volatile("cp.async.commit_group;" ::: "memory")
#define CP_WAIT(n)  asm volatile("cp.async.wait_group %0;" :: "n"(n) : "memory")

__device__ __forceinline__ void ldsm4(uint32_t& r0, uint32_t& r1, uint32_t& r2, uint32_t& r3,
                                      uint32_t addr) {
    asm volatile("ldmatrix.sync.aligned.m8n8.x4.shared.b16 {%0,%1,%2,%3}, [%4];"
                 : "=r"(r0), "=r"(r1), "=r"(r2), "=r"(r3) : "r"(addr));
}
__device__ __forceinline__ void ldsm4t(uint32_t& r0, uint32_t& r1, uint32_t& r2, uint32_t& r3,
                                       uint32_t addr) {
    asm volatile("ldmatrix.sync.aligned.m8n8.x4.trans.shared.b16 {%0,%1,%2,%3}, [%4];"
                 : "=r"(r0), "=r"(r1), "=r"(r2), "=r"(r3) : "r"(addr));
}
__device__ __forceinline__ void mma16816(float* c, uint32_t a0, uint32_t a1, uint32_t a2,
                                         uint32_t a3, uint32_t b0, uint32_t b1) {
    asm volatile(
        "mma.sync.aligned.m16n8k16.row.col.f32.bf16.bf16.f32 "
        "{%0,%1,%2,%3}, {%4,%5,%6,%7}, {%8,%9}, {%0,%1,%2,%3};"
        : "+f"(c[0]), "+f"(c[1]), "+f"(c[2]), "+f"(c[3])
        : "r"(a0), "r"(a1), "r"(a2), "r"(a3), "r"(b0), "r"(b1));
}
__device__ __forceinline__ void split2(float v0, float v1, uint32_t& hi, uint32_t& lo) {
    __nv_bfloat16 h0 = __float2bfloat16(v0), h1 = __float2bfloat16(v1);
    float r0 = v0 - __bfloat162float(h0), r1 = v1 - __bfloat162float(h1);
    __nv_bfloat162 th; th.x = h0; th.y = h1;
    hi = *reinterpret_cast<uint32_t*>(&th);
    __nv_bfloat162 tl; tl.x = __float2bfloat16(r0); tl.y = __float2bfloat16(r1);
    lo = *reinterpret_cast<uint32_t*>(&tl);
}

// ---------------- vectorized fp32 -> bf16 hi/lo converters --------------------
__global__ void cvt_b16(const float* __restrict__ x, __nv_bfloat16* __restrict__ hi,
                        __nv_bfloat16* __restrict__ lo, long n)
{
    long n4 = n >> 2;
    const float4* x4 = (const float4*)x;
    __nv_bfloat162* h2 = (__nv_bfloat162*)hi;
    __nv_bfloat162* l2 = (__nv_bfloat162*)lo;
    for (long i = (long)blockIdx.x * blockDim.x + threadIdx.x; i < n4;
         i += (long)gridDim.x * blockDim.x) {
        float4 v = x4[i];
        __nv_bfloat162 ha; ha.x = __float2bfloat16(v.x); ha.y = __float2bfloat16(v.y);
        __nv_bfloat162 hb; hb.x = __float2bfloat16(v.z); hb.y = __float2bfloat16(v.w);
        __nv_bfloat162 la; la.x = __float2bfloat16(v.x - __bfloat162float(ha.x));
        la.y = __float2bfloat16(v.y - __bfloat162float(ha.y));
        __nv_bfloat162 lb; lb.x = __float2bfloat16(v.z - __bfloat162float(hb.x));
        lb.y = __float2bfloat16(v.w - __bfloat162float(hb.y));
        h2[2 * i] = ha; h2[2 * i + 1] = hb;
        l2[2 * i] = la; l2[2 * i + 1] = lb;
    }
}

__global__ void rmsnorm_b16(const float* __restrict__ x, const float* __restrict__ w,
                            __nv_bfloat16* __restrict__ hi, __nv_bfloat16* __restrict__ lo,
                            int cols, int strideIn, int strideOut)
{
    int row = blockIdx.x;
    int t = threadIdx.x;
    const float4* xr = (const float4*)(x + (long)row * strideIn);
    const float4* w4 = (const float4*)w;
    int c4 = cols >> 2;
    float ss = 0.f;
    for (int c = t; c < c4; c += 256) {
        float4 v = xr[c];
        ss = fmaf(v.x, v.x, fmaf(v.y, v.y, fmaf(v.z, v.z, fmaf(v.w, v.w, ss))));
    }
    __shared__ float red[256];
    red[t] = ss; __syncthreads();
    for (int s = 128; s > 0; s >>= 1) { if (t < s) red[t] += red[t + s]; __syncthreads(); }
    float scale = rsqrtf(red[0] / (float)cols + 1e-6f);
    __nv_bfloat162* hr = (__nv_bfloat162*)(hi + (long)row * strideOut);
    __nv_bfloat162* lr = (__nv_bfloat162*)(lo + (long)row * strideOut);
    for (int c = t; c < c4; c += 256) {
        float4 v = xr[c];
        float4 wv = w4[c];
        float a = v.x * scale * wv.x, b = v.y * scale * wv.y;
        float d = v.z * scale * wv.z, e = v.w * scale * wv.w;
        __nv_bfloat162 ha; ha.x = __float2bfloat16(a); ha.y = __float2bfloat16(b);
        __nv_bfloat162 hb; hb.x = __float2bfloat16(d); hb.y = __float2bfloat16(e);
        __nv_bfloat162 la; la.x = __float2bfloat16(a - __bfloat162float(ha.x));
        la.y = __float2bfloat16(b - __bfloat162float(ha.y));
        __nv_bfloat162 lb; lb.x = __float2bfloat16(d - __bfloat162float(hb.x));
        lb.y = __float2bfloat16(e - __bfloat162float(hb.y));
        hr[2 * c] = ha; hr[2 * c + 1] = hb;
        lr[2 * c] = la; lr[2 * c + 1] = lb;
    }
}

// ---------------- mma.sync bf16x3 GEMM, 3-stage pipeline ----------------------
// CTA tile 128x128, Kc=32, 256 threads (8 warps, 2x4), warp tile 64x32.
#define GPADB 80
#define GT_BYTES (128 * GPADB)      // 10240
#define GS_BYTES (4 * GT_BYTES)     // 40960 per stage
#define GSTAGES 3
#define GEMM_SMEM (GSTAGES * GS_BYTES)  // 122880

__device__ __forceinline__ void g_fill(uint32_t dstBase, const __nv_bfloat16* __restrict__ src,
                                       long ld, int rmax, int t)
{
#pragma unroll
    for (int i = 0; i < 2; ++i) {
        int id = t + 256 * i;
        int row = id >> 2, ch = id & 3;
        bool ok = row < rmax;
        const __nv_bfloat16* g = src + (long)(ok ? row : 0) * ld + ch * 8;
        cpa16(dstBase + row * GPADB + ch * 16, g, ok ? 16 : 0);
    }
}

__global__ __launch_bounds__(256, 1)
void gemm_mma(const __nv_bfloat16* __restrict__ Ah, const __nv_bfloat16* __restrict__ Al, int lda,
              const __nv_bfloat16* __restrict__ Bh, const __nv_bfloat16* __restrict__ Bl,
              float* __restrict__ C, int M, int N, int K,
              const float* __restrict__ D, float beta)
{
    extern __shared__ __align__(128) char smem[];
    uint32_t sb = smem_u32(smem);
    int t = threadIdx.x;
    int warp = t >> 5, lane = t & 31;
    int wm = warp >> 2, wn = warp & 3;
    int n0 = blockIdx.x * 128, m0 = blockIdx.y * 128;
    int nc = K / 32;

    float acc[4][4][4];
#pragma unroll
    for (int i = 0; i < 4; i++)
#pragma unroll
        for (int j = 0; j < 4; j++)
#pragma unroll
            for (int r = 0; r < 4; r++) acc[i][j][r] = 0.f;

    // prologue: stages 0 and 1 load chunks 0 and 1
#pragma unroll
    for (int s = 0; s < 2; ++s) {
        uint32_t b0 = sb + s * GS_BYTES;
        int kc0 = s * 32;
        g_fill(b0 + 0 * GT_BYTES, Ah + (long)m0 * lda + kc0, lda, M - m0, t);
        g_fill(b0 + 1 * GT_BYTES, Al + (long)m0 * lda + kc0, lda, M - m0, t);
        g_fill(b0 + 2 * GT_BYTES, Bh + (long)n0 * K + kc0, K, N - n0, t);
        g_fill(b0 + 3 * GT_BYTES, Bl + (long)n0 * K + kc0, K, N - n0, t);
        CP_COMMIT();
    }

    uint32_t aoff = (uint32_t)((wm * 64 + (lane & 15)) * GPADB + (lane >> 4) * 16);
    uint32_t boff = (uint32_t)(2 * GT_BYTES +
                               (wn * 32 + (lane & 7) + ((lane >> 4) << 3)) * GPADB +
                               ((lane >> 3) & 1) * 16);

    int stage = 0;
    for (int c = 0; c < nc; ++c) {
        CP_WAIT(1);
        __syncthreads();
        // prefetch chunk c+2 into the stage freed at iter c-1
        if (c + 2 < nc) {
            int ps = stage + 2; if (ps >= GSTAGES) ps -= GSTAGES;
            uint32_t bn = sb + ps * GS_BYTES;
            int kc0 = (c + 2) * 32;
            g_fill(bn + 0 * GT_BYTES, Ah + (long)m0 * lda + kc0, lda, M - m0, t);
            g_fill(bn + 1 * GT_BYTES, Al + (long)m0 * lda + kc0, lda, M - m0, t);
            g_fill(bn + 2 * GT_BYTES, Bh + (long)n0 * K + kc0, K, N - n0, t);
            g_fill(bn + 3 * GT_BYTES, Bl + (long)n0 * K + kc0, K, N - n0, t);
        }
        CP_COMMIT();

        uint32_t base = sb + stage * GS_BYTES;
#pragma unroll
        for (int k16 = 0; k16 < 2; ++k16) {
            uint32_t ah[4][4], al_[4][4];
#pragma unroll
            for (int im = 0; im < 4; ++im) {
                uint32_t addr = base + aoff + im * 16 * GPADB + k16 * 32;
                ldsm4(ah[im][0], ah[im][1], ah[im][2], ah[im][3], addr);
                ldsm4(al_[im][0], al_[im][1], al_[im][2], al_[im][3], addr + GT_BYTES);
            }
            uint32_t bh[4][2], bl[4][2];
#pragma unroll
            for (int j2 = 0; j2 < 2; ++j2) {
                uint32_t addr = base + boff + j2 * 16 * GPADB + k16 * 32;
                uint32_t r0, r1, r2, r3;
                ldsm4(r0, r1, r2, r3, addr);
                bh[2 * j2][0] = r0; bh[2 * j2][1] = r1;
                bh[2 * j2 + 1][0] = r2; bh[2 * j2 + 1][1] = r3;
                ldsm4(r0, r1, r2, r3, addr + GT_BYTES);
                bl[2 * j2][0] = r0; bl[2 * j2][1] = r1;
                bl[2 * j2 + 1][0] = r2; bl[2 * j2 + 1][1] = r3;
            }
#pragma unroll
            for (int im = 0; im < 4; ++im)
#pragma unroll
                for (int jn = 0; jn < 4; ++jn) {
                    mma16816(acc[im][jn], ah[im][0], ah[im][1], ah[im][2], ah[im][3],
                             bh[jn][0], bh[jn][1]);
                    mma16816(acc[im][jn], ah[im][0], ah[im][1], ah[im][2], ah[im][3],
                             bl[jn][0], bl[jn][1]);
                    mma16816(acc[im][jn], al_[im][0], al_[im][1], al_[im][2], al_[im][3],
                             bh[jn][0], bh[jn][1]);
                }
        }
        if (++stage >= GSTAGES) stage = 0;
    }

    // epilogue
#pragma unroll
    for (int im = 0; im < 4; ++im) {
        int row0 = m0 + wm * 64 + im * 16 + (lane >> 2);
#pragma unroll
        for (int jn = 0; jn < 4; ++jn) {
            int col = n0 + wn * 32 + jn * 8 + (lane & 3) * 2;
            if (col < N) {
                float2 v0 = make_float2(acc[im][jn][0], acc[im][jn][1]);
                float2 v1 = make_float2(acc[im][jn][2], acc[im][jn][3]);
                if (D) {
                    float2 d0 = *(const float2*)&D[(long)row0 * N + col];
                    float2 d1 = *(const float2*)&D[(long)(row0 + 8) * N + col];
                    v0.x = fmaf(beta, d0.x, v0.x); v0.y = fmaf(beta, d0.y, v0.y);
                    v1.x = fmaf(beta, d1.x, v1.x); v1.y = fmaf(beta, d1.y, v1.y);
                }
                *(float2*)&C[(long)row0 * N + col] = v0;
                *(float2*)&C[(long)(row0 + 8) * N + col] = v1;
            }
        }
    }
}

// ---------------- RoPE + scatter ----------------------------------------------
__global__ void rope_scatter(const float* __restrict__ qin,  // [s][3072]
                             const float* __restrict__ ckv,  // [s][576]
                             const float* __restrict__ kvin, // [s][4096]
                             const int* __restrict__ pos_ids,
                             __nv_bfloat16* __restrict__ qh, __nv_bfloat16* __restrict__ ql,
                             float* __restrict__ kout,
                             __nv_bfloat16* __restrict__ kh, __nv_bfloat16* __restrict__ kl,
                             float* __restrict__ vout,
                             __nv_bfloat16* __restrict__ vh, __nv_bfloat16* __restrict__ vl)
{
    int s = blockIdx.x;
    int t = threadIdx.x;
    __shared__ float cs[32], sn[32], kr[64];
    if (t < 32) {
        double invf = exp(-(double)t * 0.28782313662425575); // ln(10000)/32
        double ang = (double)pos_ids[s] * invf;
        cs[t] = (float)cos(ang);
        sn[t] = (float)sin(ang);
    }
    __syncthreads();
    if (t < 32) {
        float x0 = ckv[s * 576 + 512 + 2 * t];
        float x1 = ckv[s * 576 + 512 + 2 * t + 1];
        kr[t]      = x0 * cs[t] - x1 * sn[t];
        kr[32 + t] = x1 * cs[t] + x0 * sn[t];
    }
    __syncthreads();
    for (int idx = t; idx < 512; idx += 256) {
        int h = idx >> 5, j = idx & 31;
        const float* qb = qin + (long)s * 3072 + h * 192;
        float x0 = qb[128 + 2 * j], x1 = qb[128 + 2 * j + 1];
        float a = x0 * cs[j] - x1 * sn[j];
        float b = x1 * cs[j] + x0 * sn[j];
        long o = ((long)h * SEQ + s) * 192;
        __nv_bfloat16 ha = __float2bfloat16(a), hb = __float2bfloat16(b);
        qh[o + 128 + j] = ha; ql[o + 128 + j] = __float2bfloat16(a - __bfloat162float(ha));
        qh[o + 160 + j] = hb; ql[o + 160 + j] = __float2bfloat16(b - __bfloat162float(hb));
    }
    for (int idx = t; idx < 2048; idx += 256) {
        int h = idx >> 7, d = idx & 127;
        float v = qin[(long)s * 3072 + h * 192 + d];
        long o = ((long)h * SEQ + s) * 192 + d;
        __nv_bfloat16 hv = __float2bfloat16(v);
        qh[o] = hv; ql[o] = __float2bfloat16(v - __bfloat162float(hv));
    }
    for (int idx = t; idx < 16 * 192; idx += 256) {
        int h = idx / 192, d = idx - h * 192;
        float v = (d < 128) ? kvin[(long)s * 4096 + h * 256 + d] : kr[d - 128];
        long o = ((long)h * SEQ + s) * 192 + d;
        kout[o] = v;
        __nv_bfloat16 hv = __float2bfloat16(v);
        kh[o] = hv; kl[o] = __float2bfloat16(v - __bfloat162float(hv));
    }
    for (int idx = t; idx < 2048; idx += 256) {
        int h = idx >> 7, d = idx & 127;
        float v = kvin[(long)s * 4096 + h * 256 + 128 + d];
        long o = ((long)h * SEQ + s) * 128 + d;
        vout[o] = v;
        __nv_bfloat16 hv = __float2bfloat16(v);
        vh[o] = hv; vl[o] = __float2bfloat16(v - __bfloat162float(hv));
    }
}

// ---------------- flash attention, double-buffered K/V ------------------------
#define FPADB 400   // (192+8)*2 bytes per smem row (Q/K)
#define VPADB 272   // (128+8)*2 bytes per smem row (V)
#define QT_B (64 * FPADB)           // 25600
#define VT_B (64 * VPADB)           // 17408
#define SQH 0
#define SQL QT_B
#define KV_BASE (2 * QT_B)          // 51200
#define KV_STAGE (2 * QT_B + 2 * VT_B)  // 86016
#define FLASH_SMEM (KV_BASE + 2 * KV_STAGE)  // 223232

__global__ __launch_bounds__(128, 1)
void flash_mma(const __nv_bfloat16* __restrict__ Qh_g, const __nv_bfloat16* __restrict__ Ql_g,
               const __nv_bfloat16* __restrict__ Kh_g, const __nv_bfloat16* __restrict__ Kl_g,
               const __nv_bfloat16* __restrict__ Vh_g, const __nv_bfloat16* __restrict__ Vl_g,
               __nv_bfloat16* __restrict__ Oh_g, __nv_bfloat16* __restrict__ Ol_g)
{
    extern __shared__ __align__(128) char smem[];
    uint32_t sb = smem_u32(smem);
    int qt = blockIdx.x, h = blockIdx.y;
    int q0 = qt * 64;
    int t = threadIdx.x;
    int warp = t >> 5, lane = t & 31;

    const __nv_bfloat16* Kgh = Kh_g + (long)h * SEQ * 192;
    const __nv_bfloat16* Kgl = Kl_g + (long)h * SEQ * 192;
    const __nv_bfloat16* Vgh = Vh_g + (long)h * SEQ * 128;
    const __nv_bfloat16* Vgl = Vl_g + (long)h * SEQ * 128;

    // Q tile (hi+lo)
    {
        const __nv_bfloat16* qg = Qh_g + ((long)h * SEQ + q0) * 192;
        const __nv_bfloat16* qg2 = Ql_g + ((long)h * SEQ + q0) * 192;
#pragma unroll
        for (int i = 0; i < 12; ++i) {
            int id = t + 128 * i;
            int row = id / 24, ch = id % 24;
            cpa16(sb + SQH + row * FPADB + ch * 16, qg + row * 192 + ch * 8, 16);
            cpa16(sb + SQL + row * FPADB + ch * 16, qg2 + row * 192 + ch * 8, 16);
        }
        CP_COMMIT();
    }
    // KV chunk 0 -> stage 0
    {
        uint32_t kvb = sb + KV_BASE;
#pragma unroll
        for (int i = 0; i < 12; ++i) {
            int id = t + 128 * i;
            int row = id / 24, ch = id % 24;
            cpa16(kvb + row * FPADB + ch * 16, Kgh + (long)row * 192 + ch * 8, 16);
            cpa16(kvb + QT_B + row * FPADB + ch * 16, Kgl + (long)row * 192 + ch * 8, 16);
        }
#pragma unroll
        for (int i = 0; i < 8; ++i) {
            int id = t + 128 * i;
            int row = id >> 4, ch = id & 15;
            cpa16(kvb + 2 * QT_B + row * VPADB + ch * 16, Vgh + (long)row * 128 + ch * 8, 16);
            cpa16(kvb + 2 * QT_B + VT_B + row * VPADB + ch * 16, Vgl + (long)row * 128 + ch * 8, 16);
        }
        CP_COMMIT();
    }

    float o[16][4];
#pragma unroll
    for (int i = 0; i < 16; i++)
#pragma unroll
        for (int r = 0; r < 4; r++) o[i][r] = 0.f;
    float mrow[2] = {-1e30f, -1e30f};
    float lrow[2] = {0.f, 0.f};

    uint32_t qoff = (uint32_t)(SQH + (warp * 16 + (lane & 15)) * FPADB + (lane >> 4) * 16);
    uint32_t koff = (uint32_t)(((lane & 7) + ((lane >> 4) << 3)) * FPADB +
                               ((lane >> 3) & 1) * 16);
    uint32_t voff = (uint32_t)(((lane & 7) + (((lane >> 3) & 1) << 3)) * VPADB +
                               ((lane >> 4) << 3) * 2);

    int rA = (lane >> 2);
    int colq = (lane & 3) * 2;

    for (int kt = 0; kt <= qt; ++kt) {
        __syncthreads();   // all warps finished reading stage (kt+1)&1 in iter kt-1
        if (kt + 1 <= qt) {
            int k1 = (kt + 1) * 64;
            uint32_t kvb = sb + KV_BASE + ((kt + 1) & 1) * KV_STAGE;
#pragma unroll
            for (int i = 0; i < 12; ++i) {
                int id = t + 128 * i;
                int row = id / 24, ch = id % 24;
                cpa16(kvb + row * FPADB + ch * 16, Kgh + (long)(k1 + row) * 192 + ch * 8, 16);
                cpa16(kvb + QT_B + row * FPADB + ch * 16, Kgl + (long)(k1 + row) * 192 + ch * 8, 16);
            }
#pragma unroll
            for (int i = 0; i < 8; ++i) {
                int id = t + 128 * i;
                int row = id >> 4, ch = id & 15;
                cpa16(kvb + 2 * QT_B + row * VPADB + ch * 16,
                      Vgh + (long)(k1 + row) * 128 + ch * 8, 16);
                cpa16(kvb + 2 * QT_B + VT_B + row * VPADB + ch * 16,
                      Vgl + (long)(k1 + row) * 128 + ch * 8, 16);
            }
        }
        CP_COMMIT();
        CP_WAIT(1);
        __syncthreads();

        int k0 = kt * 64;
        uint32_t kvb = sb + KV_BASE + (kt & 1) * KV_STAGE;

        // ---- S = Q @ K^T ----
        float sc[8][4];
#pragma unroll
        for (int j = 0; j < 8; j++)
#pragma unroll
            for (int r = 0; r < 4; r++) sc[j][r] = 0.f;

#pragma unroll 1
        for (int k16 = 0; k16 < 12; ++k16) {
            uint32_t qfh[4], qfl[4];
            uint32_t addr = sb + qoff + k16 * 32;
            ldsm4(qfh[0], qfh[1], qfh[2], qfh[3], addr);
            ldsm4(qfl[0], qfl[1], qfl[2], qfl[3], addr + QT_B);
            uint32_t kbh[8][2], kbl[8][2];
#pragma unroll
            for (int j2 = 0; j2 < 4; ++j2) {
                uint32_t ka = kvb + koff + j2 * 16 * FPADB + k16 * 32;
                uint32_t r0, r1, r2, r3;
                ldsm4(r0, r1, r2, r3, ka);
                kbh[2 * j2][0] = r0; kbh[2 * j2][1] = r1;
                kbh[2 * j2 + 1][0] = r2; kbh[2 * j2 + 1][1] = r3;
                ldsm4(r0, r1, r2, r3, ka + QT_B);
                kbl[2 * j2][0] = r0; kbl[2 * j2][1] = r1;
                kbl[2 * j2 + 1][0] = r2; kbl[2 * j2 + 1][1] = r3;
            }
#pragma unroll
            for (int j = 0; j < 8; ++j) {
                mma16816(sc[j], qfh[0], qfh[1], qfh[2], qfh[3], kbh[j][0], kbh[j][1]);
                mma16816(sc[j], qfh[0], qfh[1], qfh[2], qfh[3], kbl[j][0], kbl[j][1]);
                mma16816(sc[j], qfl[0], qfl[1], qfl[2], qfl[3], kbh[j][0], kbh[j][1]);
            }
        }

        int rowA = q0 + warp * 16 + rA;
        int rowB = rowA + 8;
#pragma unroll
        for (int j = 0; j < 8; ++j) {
#pragma unroll
            for (int r = 0; r < 4; r++) sc[j][r] *= SM_SCALE;
            if (kt == qt) {
                int col = k0 + j * 8 + colq;
                if (col > rowA)     sc[j][0] = -1e30f;
                if (col + 1 > rowA) sc[j][1] = -1e30f;
                if (col > rowB)     sc[j][2] = -1e30f;
                if (col + 1 > rowB) sc[j][3] = -1e30f;
            }
        }
        float mxa = -1e30f, mxb = -1e30f;
#pragma unroll
        for (int j = 0; j < 8; ++j) {
            mxa = fmaxf(mxa, fmaxf(sc[j][0], sc[j][1]));
            mxb = fmaxf(mxb, fmaxf(sc[j][2], sc[j][3]));
        }
        mxa = fmaxf(mxa, __shfl_xor_sync(0xffffffffu, mxa, 1));
        mxa = fmaxf(mxa, __shfl_xor_sync(0xffffffffu, mxa, 2));
        mxb = fmaxf(mxb, __shfl_xor_sync(0xffffffffu, mxb, 1));
        mxb = fmaxf(mxb, __shfl_xor_sync(0xffffffffu, mxb, 2));
        float mna = fmaxf(mrow[0], mxa), mnb = fmaxf(mrow[1], mxb);
        float ala = __expf(mrow[0] - mna), alb = __expf(mrow[1] - mnb);
        mrow[0] = mna; mrow[1] = mnb;

        float suma = 0.f, sumb = 0.f;
#pragma unroll
        for (int j = 0; j < 8; ++j) {
            sc[j][0] = __expf(sc[j][0] - mna);
            sc[j][1] = __expf(sc[j][1] - mna);
            sc[j][2] = __expf(sc[j][2] - mnb);
            sc[j][3] = __expf(sc[j][3] - mnb);
            suma += sc[j][0] + sc[j][1];
            sumb += sc[j][2] + sc[j][3];
        }
        suma += __shfl_xor_sync(0xffffffffu, suma, 1);
        suma += __shfl_xor_sync(0xffffffffu, suma, 2);
        sumb += __shfl_xor_sync(0xffffffffu, sumb, 1);
        sumb += __shfl_xor_sync(0xffffffffu, sumb, 2);
        lrow[0] = lrow[0] * ala + suma;
        lrow[1] = lrow[1] * alb + sumb;
#pragma unroll
        for (int nb = 0; nb < 16; ++nb) {
            o[nb][0] *= ala; o[nb][1] *= ala;
            o[nb][2] *= alb; o[nb][3] *= alb;
        }

        uint32_t pah[4][4], pal[4][4];
#pragma unroll
        for (int j = 0; j < 4; ++j) {
            split2(sc[2 * j][0],     sc[2 * j][1],     pah[j][0], pal[j][0]);
            split2(sc[2 * j][2],     sc[2 * j][3],     pah[j][1], pal[j][1]);
            split2(sc[2 * j + 1][0], sc[2 * j + 1][1], pah[j][2], pal[j][2]);
            split2(sc[2 * j + 1][2], sc[2 * j + 1][3], pah[j][3], pal[j][3]);
        }

        // ---- O += P @ V ----
        uint32_t vbase = kvb + 2 * QT_B;
#pragma unroll 1
        for (int j = 0; j < 4; ++j) {
#pragma unroll
            for (int nb2 = 0; nb2 < 8; ++nb2) {
                uint32_t va = vbase + voff + j * 16 * VPADB + nb2 * 32;
                uint32_t h0, h1, h2, h3, l0, l1, l2, l3;
                ldsm4t(h0, h1, h2, h3, va);
                ldsm4t(l0, l1, l2, l3, va + VT_B);
                mma16816(o[2 * nb2],     pah[j][0], pah[j][1], pah[j][2], pah[j][3], h0, h1);
                mma16816(o[2 * nb2],     pah[j][0], pah[j][1], pah[j][2], pah[j][3], l0, l1);
                mma16816(o[2 * nb2],     pal[j][0], pal[j][1], pal[j][2], pal[j][3], h0, h1);
                mma16816(o[2 * nb2 + 1], pah[j][0], pah[j][1], pah[j][2], pah[j][3], h2, h3);
                mma16816(o[2 * nb2 + 1], pah[j][0], pah[j][1], pah[j][2], pah[j][3], l2, l3);
                mma16816(o[2 * nb2 + 1], pal[j][0], pal[j][1], pal[j][2], pal[j][3], h2, h3);
            }
        }
    }

    float inva = 1.0f / lrow[0], invb = 1.0f / lrow[1];
    int rowA = q0 + warp * 16 + rA;
    int rowB = rowA + 8;
#pragma unroll
    for (int nb = 0; nb < 16; ++nb) {
        int col = h * 128 + nb * 8 + colq;
        uint32_t hA, lA, hB, lB;
        split2(o[nb][0] * inva, o[nb][1] * inva, hA, lA);
        split2(o[nb][2] * invb, o[nb][3] * invb, hB, lB);
        *(uint32_t*)&Oh_g[(long)rowA * 2048 + col] = hA;
        *(uint32_t*)&Ol_g[(long)rowA * 2048 + col] = lA;
        *(uint32_t*)&Oh_g[(long)rowB * 2048 + col] = hB;
        *(uint32_t*)&Ol_g[(long)rowB * 2048 + col] = lB;
    }
}

// ---------------- launch ------------------------------------------------------
extern "C" void kernel_launch(void* const* d_in, const int* in_sizes, int n_in,
                              void* d_out, int out_size)
{
    const float* hidden   = (const float*)d_in[0];
    const int*   pos      = (const int*)d_in[1];
    const float* ln_w     = (const float*)d_in[3];
    const float* wq_a     = (const float*)d_in[4];
    const float* q_a_ln   = (const float*)d_in[5];
    const float* wq_b     = (const float*)d_in[6];
    const float* wkv_a    = (const float*)d_in[7];
    const float* kv_a_ln  = (const float*)d_in[8];
    const float* wkv_b    = (const float*)d_in[9];
    const float* wo       = (const float*)d_in[10];

    float* out   = (float*)d_out;
    float* k_out = out + (long)SEQ * HIDDEN;
    float* v_out = k_out + (long)NHEADS * SEQ * QKD;

    float *p_qa, *p_q, *p_ckv, *p_kv;
    cudaGetSymbolAddress((void**)&p_qa, g_qa);
    cudaGetSymbolAddress((void**)&p_q, g_q);
    cudaGetSymbolAddress((void**)&p_ckv, g_ckv);
    cudaGetSymbolAddress((void**)&p_kv, g_kv);

    __nv_bfloat16 *h_hi, *h_lo, *qa_hi, *qa_lo, *ckvn_hi, *ckvn_lo, *attn_hi, *attn_lo;
    __nv_bfloat16 *qf_hi, *qf_lo, *k_hi, *k_lo, *v_hi, *v_lo;
    __nv_bfloat16 *wqa_hi, *wqa_lo, *wqb_hi, *wqb_lo, *wkva_hi, *wkva_lo, *wkvb_hi, *wkvb_lo, *wo_hi, *wo_lo;
    cudaGetSymbolAddress((void**)&h_hi, g_h_hi);       cudaGetSymbolAddress((void**)&h_lo, g_h_lo);
    cudaGetSymbolAddress((void**)&qa_hi, g_qa_hi);     cudaGetSymbolAddress((void**)&qa_lo, g_qa_lo);
    cudaGetSymbolAddress((void**)&ckvn_hi, g_ckvn_hi); cudaGetSymbolAddress((void**)&ckvn_lo, g_ckvn_lo);
    cudaGetSymbolAddress((void**)&attn_hi, g_attn_hi); cudaGetSymbolAddress((void**)&attn_lo, g_attn_lo);
    cudaGetSymbolAddress((void**)&qf_hi, g_qf_hi);     cudaGetSymbolAddress((void**)&qf_lo, g_qf_lo);
    cudaGetSymbolAddress((void**)&k_hi, g_k_hi);       cudaGetSymbolAddress((void**)&k_lo, g_k_lo);
    cudaGetSymbolAddress((void**)&v_hi, g_v_hi);       cudaGetSymbolAddress((void**)&v_lo, g_v_lo);
    cudaGetSymbolAddress((void**)&wqa_hi, g_wqa_hi);   cudaGetSymbolAddress((void**)&wqa_lo, g_wqa_lo);
    cudaGetSymbolAddress((void**)&wqb_hi, g_wqb_hi);   cudaGetSymbolAddress((void**)&wqb_lo, g_wqb_lo);
    cudaGetSymbolAddress((void**)&wkva_hi, g_wkva_hi); cudaGetSymbolAddress((void**)&wkva_lo, g_wkva_lo);
    cudaGetSymbolAddress((void**)&wkvb_hi, g_wkvb_hi); cudaGetSymbolAddress((void**)&wkvb_lo, g_wkvb_lo);
    cudaGetSymbolAddress((void**)&wo_hi, g_wo_hi);     cudaGetSymbolAddress((void**)&wo_lo, g_wo_lo);

    cudaFuncSetAttribute(gemm_mma, cudaFuncAttributeMaxDynamicSharedMemorySize, GEMM_SMEM);
    cudaFuncSetAttribute(flash_mma, cudaFuncAttributeMaxDynamicSharedMemorySize, FLASH_SMEM);

    cvt_b16<<<592, 256>>>(wq_a,  wqa_hi,  wqa_lo,  (long)QLORA * HIDDEN);
    cvt_b16<<<592, 256>>>(wq_b,  wqb_hi,  wqb_lo,  (long)3072 * QLORA);
    cvt_b16<<<592, 256>>>(wkv_a, wkva_hi, wkva_lo, (long)576 * HIDDEN);
    cvt_b16<<<592, 256>>>(wkv_b, wkvb_hi, wkvb_lo, (long)4096 * KVLORA);
    cvt_b16<<<592, 256>>>(wo,    wo_hi,   wo_lo,   (long)HIDDEN * 2048);

    rmsnorm_b16<<<SEQ, 256>>>(hidden, ln_w, h_hi, h_lo, HIDDEN, HIDDEN, HIDDEN);
    gemm_mma<<<dim3(QLORA / 128, SEQ / 128), 256, GEMM_SMEM>>>(
        h_hi, h_lo, HIDDEN, wqa_hi, wqa_lo, p_qa, SEQ, QLORA, HIDDEN, nullptr, 0.f);
    rmsnorm_b16<<<SEQ, 256>>>(p_qa, q_a_ln, qa_hi, qa_lo, QLORA, QLORA, QLORA);
    gemm_mma<<<dim3(3072 / 128, SEQ / 128), 256, GEMM_SMEM>>>(
        qa_hi, qa_lo, QLORA, wqb_hi, wqb_lo, p_q, SEQ, 3072, QLORA, nullptr, 0.f);
    gemm_mma<<<dim3(5, SEQ / 128), 256, GEMM_SMEM>>>(
        h_hi, h_lo, HIDDEN, wkva_hi, wkva_lo, p_ckv, SEQ, 576, HIDDEN, nullptr, 0.f);
    rmsnorm_b16<<<SEQ, 256>>>(p_ckv, kv_a_ln, ckvn_hi, ckvn_lo, KVLORA, 576, KVLORA);
    gemm_mma<<<dim3(4096 / 128, SEQ / 128), 256, GEMM_SMEM>>>(
        ckvn_hi, ckvn_lo, KVLORA, wkvb_hi, wkvb_lo, p_kv, SEQ, 4096, KVLORA, nullptr, 0.f);
    rope_scatter<<<SEQ, 256>>>(p_q, p_ckv, p_kv, pos, qf_hi, qf_lo,
                               k_out, k_hi, k_lo, v_out, v_hi, v_lo);
    flash_mma<<<dim3(SEQ / 64, NHEADS), 128, FLASH_SMEM>>>(
        qf_hi, qf_lo, k_hi, k_lo, v_hi, v_lo, attn_hi, attn_lo);
    gemm_mma<<<dim3(HIDDEN / 128, SEQ / 128), 256, GEMM_SMEM>>>(
        attn_hi, attn_lo, 2048, wo_hi, wo_lo, out, SEQ, HIDDEN, 2048,
        hidden, RESID_SCALE);
}

// round 5
// speedup vs baseline: 5.1406x; 1.2307x over previous
#include <cuda_runtime.h>
#include <cuda_bf16.h>
#include <math.h>
#include <stdint.h>

#define HIDDEN 5120
#define NHEADS 16
#define QLORA  1536
#define KVLORA 512
#define NOPE   128
#define ROPE_D 64
#define QKD    192
#define VDIM   128
#define SEQ    2048
#define QKVN   2112   // QLORA + 576 (fused first-stage projection width)
#define SM_SCALE 0.07216878364870322f  // 192^-0.5
#define RESID_SCALE 0.125f

// ---------------- scratch ----------------------------------------------------
static __device__ float g_qackv[SEQ * QKVN];   // [s][1536 qa | 512 ckv | 64 kpe]
static __device__ float g_q[SEQ * NHEADS * QKD];
static __device__ float g_kv[SEQ * 4096];

static __device__ __nv_bfloat16 g_h_hi[SEQ * HIDDEN],    g_h_lo[SEQ * HIDDEN];
static __device__ __nv_bfloat16 g_qa_hi[SEQ * QLORA],    g_qa_lo[SEQ * QLORA];
static __device__ __nv_bfloat16 g_ckvn_hi[SEQ * KVLORA], g_ckvn_lo[SEQ * KVLORA];
static __device__ __nv_bfloat16 g_attn_hi[SEQ * 2048],   g_attn_lo[SEQ * 2048];
static __device__ __nv_bfloat16 g_qf_hi[NHEADS * SEQ * QKD], g_qf_lo[NHEADS * SEQ * QKD];
static __device__ __nv_bfloat16 g_k_hi[NHEADS * SEQ * QKD],  g_k_lo[NHEADS * SEQ * QKD];
static __device__ __nv_bfloat16 g_v_hi[NHEADS * SEQ * VDIM], g_v_lo[NHEADS * SEQ * VDIM];

static __device__ __nv_bfloat16 g_wqkva_hi[QKVN * HIDDEN], g_wqkva_lo[QKVN * HIDDEN];
static __device__ __nv_bfloat16 g_wqb_hi[3072 * QLORA],    g_wqb_lo[3072 * QLORA];
static __device__ __nv_bfloat16 g_wkvb_hi[4096 * KVLORA],  g_wkvb_lo[4096 * KVLORA];
static __device__ __nv_bfloat16 g_wo_hi[HIDDEN * 2048],    g_wo_lo[HIDDEN * 2048];

// ---------------- helpers ----------------------------------------------------
__device__ __forceinline__ uint32_t smem_u32(const void* p) {
    return (uint32_t)__cvta_generic_to_shared(p);
}
__device__ __forceinline__ void cpa16(uint32_t dst, const void* src, int sz) {
    asm volatile("cp.async.cg.shared.global [%0], [%1], 16, %2;"
                 :: "r"(dst), "l"(src), "r"(sz) : "memory");
}
#define CP_COMMIT() asm volatile("cp.async.commit_group;" ::: "memory")
#define CP_WAIT(n)  asm volatile("cp.async.wait_group %0;" :: "n"(n) : "memory")

__device__ __forceinline__ void ldsm4(uint32_t& r0, uint32_t& r1, uint32_t& r2, uint32_t& r3,
                                      uint32_t addr) {
    asm volatile("ldmatrix.sync.aligned.m8n8.x4.shared.b16 {%0,%1,%2,%3}, [%4];"
                 : "=r"(r0), "=r"(r1), "=r"(r2), "=r"(r3) : "r"(addr));
}
__device__ __forceinline__ void ldsm4t(uint32_t& r0, uint32_t& r1, uint32_t& r2, uint32_t& r3,
                                       uint32_t addr) {
    asm volatile("ldmatrix.sync.aligned.m8n8.x4.trans.shared.b16 {%0,%1,%2,%3}, [%4];"
                 : "=r"(r0), "=r"(r1), "=r"(r2), "=r"(r3) : "r"(addr));
}
__device__ __forceinline__ void mma16816(float* c, uint32_t a0, uint32_t a1, uint32_t a2,
                                         uint32_t a3, uint32_t b0, uint32_t b1) {
    asm volatile(
        "mma.sync.aligned.m16n8k16.row.col.f32.bf16.bf16.f32 "
        "{%0,%1,%2,%3}, {%4,%5,%6,%7}, {%8,%9}, {%0,%1,%2,%3};"
        : "+f"(c[0]), "+f"(c[1]), "+f"(c[2]), "+f"(c[3])
        : "r"(a0), "r"(a1), "r"(a2), "r"(a3), "r"(b0), "r"(b1));
}
__device__ __forceinline__ void split2(float v0, float v1, uint32_t& hi, uint32_t& lo) {
    __nv_bfloat16 h0 = __float2bfloat16(v0), h1 = __float2bfloat16(v1);
    float r0 = v0 - __bfloat162float(h0), r1 = v1 - __bfloat162float(h1);
    __nv_bfloat162 th; th.x = h0; th.y = h1;
    hi = *reinterpret_cast<uint32_t*>(&th);
    __nv_bfloat162 tl; tl.x = __float2bfloat16(r0); tl.y = __float2bfloat16(r1);
    lo = *reinterpret_cast<uint32_t*>(&tl);
}

// ---------------- vectorized fp32 -> bf16 hi/lo converters --------------------
__global__ void cvt_b16(const float* __restrict__ x, __nv_bfloat16* __restrict__ hi,
                        __nv_bfloat16* __restrict__ lo, long n)
{
    long n4 = n >> 2;
    const float4* x4 = (const float4*)x;
    __nv_bfloat162* h2 = (__nv_bfloat162*)hi;
    __nv_bfloat162* l2 = (__nv_bfloat162*)lo;
    for (long i = (long)blockIdx.x * blockDim.x + threadIdx.x; i < n4;
         i += (long)gridDim.x * blockDim.x) {
        float4 v = x4[i];
        __nv_bfloat162 ha; ha.x = __float2bfloat16(v.x); ha.y = __float2bfloat16(v.y);
        __nv_bfloat162 hb; hb.x = __float2bfloat16(v.z); hb.y = __float2bfloat16(v.w);
        __nv_bfloat162 la; la.x = __float2bfloat16(v.x - __bfloat162float(ha.x));
        la.y = __float2bfloat16(v.y - __bfloat162float(ha.y));
        __nv_bfloat162 lb; lb.x = __float2bfloat16(v.z - __bfloat162float(hb.x));
        lb.y = __float2bfloat16(v.w - __bfloat162float(hb.y));
        h2[2 * i] = ha; h2[2 * i + 1] = hb;
        l2[2 * i] = la; l2[2 * i + 1] = lb;
    }
}

__global__ void rmsnorm_b16(const float* __restrict__ x, const float* __restrict__ w,
                            __nv_bfloat16* __restrict__ hi, __nv_bfloat16* __restrict__ lo,
                            int cols, int strideIn, int strideOut)
{
    int row = blockIdx.x;
    int t = threadIdx.x;
    const float4* xr = (const float4*)(x + (long)row * strideIn);
    const float4* w4 = (const float4*)w;
    int c4 = cols >> 2;
    float ss = 0.f;
    for (int c = t; c < c4; c += 256) {
        float4 v = xr[c];
        ss = fmaf(v.x, v.x, fmaf(v.y, v.y, fmaf(v.z, v.z, fmaf(v.w, v.w, ss))));
    }
    __shared__ float red[256];
    red[t] = ss; __syncthreads();
    for (int s = 128; s > 0; s >>= 1) { if (t < s) red[t] += red[t + s]; __syncthreads(); }
    float scale = rsqrtf(red[0] / (float)cols + 1e-6f);
    __nv_bfloat162* hr = (__nv_bfloat162*)(hi + (long)row * strideOut);
    __nv_bfloat162* lr = (__nv_bfloat162*)(lo + (long)row * strideOut);
    for (int c = t; c < c4; c += 256) {
        float4 v = xr[c];
        float4 wv = w4[c];
        float a = v.x * scale * wv.x, b = v.y * scale * wv.y;
        float d = v.z * scale * wv.z, e = v.w * scale * wv.w;
        __nv_bfloat162 ha; ha.x = __float2bfloat16(a); ha.y = __float2bfloat16(b);
        __nv_bfloat162 hb; hb.x = __float2bfloat16(d); hb.y = __float2bfloat16(e);
        __nv_bfloat162 la; la.x = __float2bfloat16(a - __bfloat162float(ha.x));
        la.y = __float2bfloat16(b - __bfloat162float(ha.y));
        __nv_bfloat162 lb; lb.x = __float2bfloat16(d - __bfloat162float(hb.x));
        lb.y = __float2bfloat16(e - __bfloat162float(hb.y));
        hr[2 * c] = ha; hr[2 * c + 1] = hb;
        lr[2 * c] = la; lr[2 * c + 1] = lb;
    }
}

// ---------------- mma.sync bf16x3 GEMM, 2 stages, 2 CTAs/SM -------------------
// CTA tile 128x128, Kc=32, 256 threads (8 warps, 2x4), warp tile 64x32.
#define GPADB 80
#define GT_BYTES (128 * GPADB)      // 10240
#define GS_BYTES (4 * GT_BYTES)     // 40960 per stage
#define GEMM_SMEM (2 * GS_BYTES)    // 81920 -> 2 CTAs/SM

__device__ __forceinline__ void g_fill(uint32_t dstBase, const __nv_bfloat16* __restrict__ src,
                                       long ld, int rmax, int t)
{
#pragma unroll
    for (int i = 0; i < 2; ++i) {
        int id = t + 256 * i;
        int row = id >> 2, ch = id & 3;
        bool ok = row < rmax;
        const __nv_bfloat16* g = src + (long)(ok ? row : 0) * ld + ch * 8;
        cpa16(dstBase + row * GPADB + ch * 16, g, ok ? 16 : 0);
    }
}

__global__ __launch_bounds__(256, 2)
void gemm_mma(const __nv_bfloat16* __restrict__ Ah, const __nv_bfloat16* __restrict__ Al, int lda,
              const __nv_bfloat16* __restrict__ Bh, const __nv_bfloat16* __restrict__ Bl,
              float* __restrict__ C, int M, int N, int K,
              const float* __restrict__ D, float beta)
{
    extern __shared__ __align__(128) char smem[];
    uint32_t sb = smem_u32(smem);
    int t = threadIdx.x;
    int warp = t >> 5, lane = t & 31;
    int wm = warp >> 2, wn = warp & 3;
    int n0 = blockIdx.x * 128, m0 = blockIdx.y * 128;
    int nc = K / 32;

    float acc[4][4][4];
#pragma unroll
    for (int i = 0; i < 4; i++)
#pragma unroll
        for (int j = 0; j < 4; j++)
#pragma unroll
            for (int r = 0; r < 4; r++) acc[i][j][r] = 0.f;

    // prologue: chunk 0 -> stage 0
    {
        g_fill(sb + 0 * GT_BYTES, Ah + (long)m0 * lda, lda, M - m0, t);
        g_fill(sb + 1 * GT_BYTES, Al + (long)m0 * lda, lda, M - m0, t);
        g_fill(sb + 2 * GT_BYTES, Bh + (long)n0 * K, K, N - n0, t);
        g_fill(sb + 3 * GT_BYTES, Bl + (long)n0 * K, K, N - n0, t);
        CP_COMMIT();
    }

    uint32_t aoff = (uint32_t)((wm * 64 + (lane & 15)) * GPADB + (lane >> 4) * 16);
    uint32_t boff = (uint32_t)(2 * GT_BYTES +
                               (wn * 32 + (lane & 7) + ((lane >> 4) << 3)) * GPADB +
                               ((lane >> 3) & 1) * 16);

    for (int c = 0; c < nc; ++c) {
        CP_WAIT(0);          // chunk c resident
        __syncthreads();     // all warps done reading stage (c+1)&1 (iter c-1)
        if (c + 1 < nc) {    // stream chunk c+1 during compute of c
            uint32_t bn = sb + ((c + 1) & 1) * GS_BYTES;
            int kc0 = (c + 1) * 32;
            g_fill(bn + 0 * GT_BYTES, Ah + (long)m0 * lda + kc0, lda, M - m0, t);
            g_fill(bn + 1 * GT_BYTES, Al + (long)m0 * lda + kc0, lda, M - m0, t);
            g_fill(bn + 2 * GT_BYTES, Bh + (long)n0 * K + kc0, K, N - n0, t);
            g_fill(bn + 3 * GT_BYTES, Bl + (long)n0 * K + kc0, K, N - n0, t);
        }
        CP_COMMIT();

        uint32_t base = sb + (c & 1) * GS_BYTES;
#pragma unroll
        for (int k16 = 0; k16 < 2; ++k16) {
            uint32_t ah[4][4], al_[4][4];
#pragma unroll
            for (int im = 0; im < 4; ++im) {
                uint32_t addr = base + aoff + im * 16 * GPADB + k16 * 32;
                ldsm4(ah[im][0], ah[im][1], ah[im][2], ah[im][3], addr);
                ldsm4(al_[im][0], al_[im][1], al_[im][2], al_[im][3], addr + GT_BYTES);
            }
            uint32_t bh[4][2], bl[4][2];
#pragma unroll
            for (int j2 = 0; j2 < 2; ++j2) {
                uint32_t addr = base + boff + j2 * 16 * GPADB + k16 * 32;
                uint32_t r0, r1, r2, r3;
                ldsm4(r0, r1, r2, r3, addr);
                bh[2 * j2][0] = r0; bh[2 * j2][1] = r1;
                bh[2 * j2 + 1][0] = r2; bh[2 * j2 + 1][1] = r3;
                ldsm4(r0, r1, r2, r3, addr + GT_BYTES);
                bl[2 * j2][0] = r0; bl[2 * j2][1] = r1;
                bl[2 * j2 + 1][0] = r2; bl[2 * j2 + 1][1] = r3;
            }
#pragma unroll
            for (int im = 0; im < 4; ++im)
#pragma unroll
                for (int jn = 0; jn < 4; ++jn) {
                    mma16816(acc[im][jn], ah[im][0], ah[im][1], ah[im][2], ah[im][3],
                             bh[jn][0], bh[jn][1]);
                    mma16816(acc[im][jn], ah[im][0], ah[im][1], ah[im][2], ah[im][3],
                             bl[jn][0], bl[jn][1]);
                    mma16816(acc[im][jn], al_[im][0], al_[im][1], al_[im][2], al_[im][3],
                             bh[jn][0], bh[jn][1]);
                }
        }
    }

    // epilogue
#pragma unroll
    for (int im = 0; im < 4; ++im) {
        int row0 = m0 + wm * 64 + im * 16 + (lane >> 2);
#pragma unroll
        for (int jn = 0; jn < 4; ++jn) {
            int col = n0 + wn * 32 + jn * 8 + (lane & 3) * 2;
            if (col < N) {
                float2 v0 = make_float2(acc[im][jn][0], acc[im][jn][1]);
                float2 v1 = make_float2(acc[im][jn][2], acc[im][jn][3]);
                if (D) {
                    float2 d0 = *(const float2*)&D[(long)row0 * N + col];
                    float2 d1 = *(const float2*)&D[(long)(row0 + 8) * N + col];
                    v0.x = fmaf(beta, d0.x, v0.x); v0.y = fmaf(beta, d0.y, v0.y);
                    v1.x = fmaf(beta, d1.x, v1.x); v1.y = fmaf(beta, d1.y, v1.y);
                }
                *(float2*)&C[(long)row0 * N + col] = v0;
                *(float2*)&C[(long)(row0 + 8) * N + col] = v1;
            }
        }
    }
}

// ---------------- RoPE + scatter ----------------------------------------------
// qackv layout per row (stride 2112): [0:1536) qa raw, [1536:2048) ckv, [2048:2112) k_pe
__global__ void rope_scatter(const float* __restrict__ qin,    // [s][3072]
                             const float* __restrict__ qackv,  // [s][2112]
                             const float* __restrict__ kvin,   // [s][4096]
                             const int* __restrict__ pos_ids,
                             __nv_bfloat16* __restrict__ qh, __nv_bfloat16* __restrict__ ql,
                             float* __restrict__ kout,
                             __nv_bfloat16* __restrict__ kh, __nv_bfloat16* __restrict__ kl,
                             float* __restrict__ vout,
                             __nv_bfloat16* __restrict__ vh, __nv_bfloat16* __restrict__ vl)
{
    int s = blockIdx.x;
    int t = threadIdx.x;
    __shared__ float cs[32], sn[32], kr[64];
    if (t < 32) {
        double invf = exp(-(double)t * 0.28782313662425575); // ln(10000)/32
        double ang = (double)pos_ids[s] * invf;
        cs[t] = (float)cos(ang);
        sn[t] = (float)sin(ang);
    }
    __syncthreads();
    if (t < 32) {
        float x0 = qackv[(long)s * QKVN + 2048 + 2 * t];
        float x1 = qackv[(long)s * QKVN + 2048 + 2 * t + 1];
        kr[t]      = x0 * cs[t] - x1 * sn[t];
        kr[32 + t] = x1 * cs[t] + x0 * sn[t];
    }
    __syncthreads();
    for (int idx = t; idx < 512; idx += 256) {
        int h = idx >> 5, j = idx & 31;
        const float* qb = qin + (long)s * 3072 + h * 192;
        float x0 = qb[128 + 2 * j], x1 = qb[128 + 2 * j + 1];
        float a = x0 * cs[j] - x1 * sn[j];
        float b = x1 * cs[j] + x0 * sn[j];
        long o = ((long)h * SEQ + s) * 192;
        __nv_bfloat16 ha = __float2bfloat16(a), hb = __float2bfloat16(b);
        qh[o + 128 + j] = ha; ql[o + 128 + j] = __float2bfloat16(a - __bfloat162float(ha));
        qh[o + 160 + j] = hb; ql[o + 160 + j] = __float2bfloat16(b - __bfloat162float(hb));
    }
    for (int idx = t; idx < 2048; idx += 256) {
        int h = idx >> 7, d = idx & 127;
        float v = qin[(long)s * 3072 + h * 192 + d];
        long o = ((long)h * SEQ + s) * 192 + d;
        __nv_bfloat16 hv = __float2bfloat16(v);
        qh[o] = hv; ql[o] = __float2bfloat16(v - __bfloat162float(hv));
    }
    for (int idx = t; idx < 16 * 192; idx += 256) {
        int h = idx / 192, d = idx - h * 192;
        float v = (d < 128) ? kvin[(long)s * 4096 + h * 256 + d] : kr[d - 128];
        long o = ((long)h * SEQ + s) * 192 + d;
        kout[o] = v;
        __nv_bfloat16 hv = __float2bfloat16(v);
        kh[o] = hv; kl[o] = __float2bfloat16(v - __bfloat162float(hv));
    }
    for (int idx = t; idx < 2048; idx += 256) {
        int h = idx >> 7, d = idx & 127;
        float v = kvin[(long)s * 4096 + h * 256 + 128 + d];
        long o = ((long)h * SEQ + s) * 128 + d;
        vout[o] = v;
        __nv_bfloat16 hv = __float2bfloat16(v);
        vh[o] = hv; vl[o] = __float2bfloat16(v - __bfloat162float(hv));
    }
}

// ---------------- flash attention, double-buffered K/V ------------------------
#define FPADB 400   // (192+8)*2 bytes per smem row (Q/K)
#define VPADB 272   // (128+8)*2 bytes per smem row (V)
#define QT_B (64 * FPADB)           // 25600
#define VT_B (64 * VPADB)           // 17408
#define SQH 0
#define SQL QT_B
#define KV_BASE (2 * QT_B)          // 51200
#define KV_STAGE (2 * QT_B + 2 * VT_B)  // 86016
#define FLASH_SMEM (KV_BASE + 2 * KV_STAGE)  // 223232

__global__ __launch_bounds__(128, 1)
void flash_mma(const __nv_bfloat16* __restrict__ Qh_g, const __nv_bfloat16* __restrict__ Ql_g,
               const __nv_bfloat16* __restrict__ Kh_g, const __nv_bfloat16* __restrict__ Kl_g,
               const __nv_bfloat16* __restrict__ Vh_g, const __nv_bfloat16* __restrict__ Vl_g,
               __nv_bfloat16* __restrict__ Oh_g, __nv_bfloat16* __restrict__ Ol_g)
{
    extern __shared__ __align__(128) char smem[];
    uint32_t sb = smem_u32(smem);
    int qt = blockIdx.x, h = blockIdx.y;
    int q0 = qt * 64;
    int t = threadIdx.x;
    int warp = t >> 5, lane = t & 31;

    const __nv_bfloat16* Kgh = Kh_g + (long)h * SEQ * 192;
    const __nv_bfloat16* Kgl = Kl_g + (long)h * SEQ * 192;
    const __nv_bfloat16* Vgh = Vh_g + (long)h * SEQ * 128;
    const __nv_bfloat16* Vgl = Vl_g + (long)h * SEQ * 128;

    {
        const __nv_bfloat16* qg = Qh_g + ((long)h * SEQ + q0) * 192;
        const __nv_bfloat16* qg2 = Ql_g + ((long)h * SEQ + q0) * 192;
#pragma unroll
        for (int i = 0; i < 12; ++i) {
            int id = t + 128 * i;
            int row = id / 24, ch = id % 24;
            cpa16(sb + SQH + row * FPADB + ch * 16, qg + row * 192 + ch * 8, 16);
            cpa16(sb + SQL + row * FPADB + ch * 16, qg2 + row * 192 + ch * 8, 16);
        }
        CP_COMMIT();
    }
    {
        uint32_t kvb = sb + KV_BASE;
#pragma unroll
        for (int i = 0; i < 12; ++i) {
            int id = t + 128 * i;
            int row = id / 24, ch = id % 24;
            cpa16(kvb + row * FPADB + ch * 16, Kgh + (long)row * 192 + ch * 8, 16);
            cpa16(kvb + QT_B + row * FPADB + ch * 16, Kgl + (long)row * 192 + ch * 8, 16);
        }
#pragma unroll
        for (int i = 0; i < 8; ++i) {
            int id = t + 128 * i;
            int row = id >> 4, ch = id & 15;
            cpa16(kvb + 2 * QT_B + row * VPADB + ch * 16, Vgh + (long)row * 128 + ch * 8, 16);
            cpa16(kvb + 2 * QT_B + VT_B + row * VPADB + ch * 16, Vgl + (long)row * 128 + ch * 8, 16);
        }
        CP_COMMIT();
    }

    float o[16][4];
#pragma unroll
    for (int i = 0; i < 16; i++)
#pragma unroll
        for (int r = 0; r < 4; r++) o[i][r] = 0.f;
    float mrow[2] = {-1e30f, -1e30f};
    float lrow[2] = {0.f, 0.f};

    uint32_t qoff = (uint32_t)(SQH + (warp * 16 + (lane & 15)) * FPADB + (lane >> 4) * 16);
    uint32_t koff = (uint32_t)(((lane & 7) + ((lane >> 4) << 3)) * FPADB +
                               ((lane >> 3) & 1) * 16);
    uint32_t voff = (uint32_t)(((lane & 7) + (((lane >> 3) & 1) << 3)) * VPADB +
                               ((lane >> 4) << 3) * 2);

    int rA = (lane >> 2);
    int colq = (lane & 3) * 2;

    for (int kt = 0; kt <= qt; ++kt) {
        __syncthreads();
        if (kt + 1 <= qt) {
            int k1 = (kt + 1) * 64;
            uint32_t kvb = sb + KV_BASE + ((kt + 1) & 1) * KV_STAGE;
#pragma unroll
            for (int i = 0; i < 12; ++i) {
                int id = t + 128 * i;
                int row = id / 24, ch = id % 24;
                cpa16(kvb + row * FPADB + ch * 16, Kgh + (long)(k1 + row) * 192 + ch * 8, 16);
                cpa16(kvb + QT_B + row * FPADB + ch * 16, Kgl + (long)(k1 + row) * 192 + ch * 8, 16);
            }
#pragma unroll
            for (int i = 0; i < 8; ++i) {
                int id = t + 128 * i;
                int row = id >> 4, ch = id & 15;
                cpa16(kvb + 2 * QT_B + row * VPADB + ch * 16,
                      Vgh + (long)(k1 + row) * 128 + ch * 8, 16);
                cpa16(kvb + 2 * QT_B + VT_B + row * VPADB + ch * 16,
                      Vgl + (long)(k1 + row) * 128 + ch * 8, 16);
            }
        }
        CP_COMMIT();
        CP_WAIT(1);
        __syncthreads();

        int k0 = kt * 64;
        uint32_t kvb = sb + KV_BASE + (kt & 1) * KV_STAGE;

        float sc[8][4];
#pragma unroll
        for (int j = 0; j < 8; j++)
#pragma unroll
            for (int r = 0; r < 4; r++) sc[j][r] = 0.f;

#pragma unroll 1
        for (int k16 = 0; k16 < 12; ++k16) {
            uint32_t qfh[4], qfl[4];
            uint32_t addr = sb + qoff + k16 * 32;
            ldsm4(qfh[0], qfh[1], qfh[2], qfh[3], addr);
            ldsm4(qfl[0], qfl[1], qfl[2], qfl[3], addr + QT_B);
            uint32_t kbh[8][2], kbl[8][2];
#pragma unroll
            for (int j2 = 0; j2 < 4; ++j2) {
                uint32_t ka = kvb + koff + j2 * 16 * FPADB + k16 * 32;
                uint32_t r0, r1, r2, r3;
                ldsm4(r0, r1, r2, r3, ka);
                kbh[2 * j2][0] = r0; kbh[2 * j2][1] = r1;
                kbh[2 * j2 + 1][0] = r2; kbh[2 * j2 + 1][1] = r3;
                ldsm4(r0, r1, r2, r3, ka + QT_B);
                kbl[2 * j2][0] = r0; kbl[2 * j2][1] = r1;
                kbl[2 * j2 + 1][0] = r2; kbl[2 * j2 + 1][1] = r3;
            }
#pragma unroll
            for (int j = 0; j < 8; ++j) {
                mma16816(sc[j], qfh[0], qfh[1], qfh[2], qfh[3], kbh[j][0], kbh[j][1]);
                mma16816(sc[j], qfh[0], qfh[1], qfh[2], qfh[3], kbl[j][0], kbl[j][1]);
                mma16816(sc[j], qfl[0], qfl[1], qfl[2], qfl[3], kbh[j][0], kbh[j][1]);
            }
        }

        int rowA = q0 + warp * 16 + rA;
        int rowB = rowA + 8;
#pragma unroll
        for (int j = 0; j < 8; ++j) {
#pragma unroll
            for (int r = 0; r < 4; r++) sc[j][r] *= SM_SCALE;
            if (kt == qt) {
                int col = k0 + j * 8 + colq;
                if (col > rowA)     sc[j][0] = -1e30f;
                if (col + 1 > rowA) sc[j][1] = -1e30f;
                if (col > rowB)     sc[j][2] = -1e30f;
                if (col + 1 > rowB) sc[j][3] = -1e30f;
            }
        }
        float mxa = -1e30f, mxb = -1e30f;
#pragma unroll
        for (int j = 0; j < 8; ++j) {
            mxa = fmaxf(mxa, fmaxf(sc[j][0], sc[j][1]));
            mxb = fmaxf(mxb, fmaxf(sc[j][2], sc[j][3]));
        }
        mxa = fmaxf(mxa, __shfl_xor_sync(0xffffffffu, mxa, 1));
        mxa = fmaxf(mxa, __shfl_xor_sync(0xffffffffu, mxa, 2));
        mxb = fmaxf(mxb, __shfl_xor_sync(0xffffffffu, mxb, 1));
        mxb = fmaxf(mxb, __shfl_xor_sync(0xffffffffu, mxb, 2));
        float mna = fmaxf(mrow[0], mxa), mnb = fmaxf(mrow[1], mxb);
        float ala = __expf(mrow[0] - mna), alb = __expf(mrow[1] - mnb);
        mrow[0] = mna; mrow[1] = mnb;

        float suma = 0.f, sumb = 0.f;
#pragma unroll
        for (int j = 0; j < 8; ++j) {
            sc[j][0] = __expf(sc[j][0] - mna);
            sc[j][1] = __expf(sc[j][1] - mna);
            sc[j][2] = __expf(sc[j][2] - mnb);
            sc[j][3] = __expf(sc[j][3] - mnb);
            suma += sc[j][0] + sc[j][1];
            sumb += sc[j][2] + sc[j][3];
        }
        suma += __shfl_xor_sync(0xffffffffu, suma, 1);
        suma += __shfl_xor_sync(0xffffffffu, suma, 2);
        sumb += __shfl_xor_sync(0xffffffffu, sumb, 1);
        sumb += __shfl_xor_sync(0xffffffffu, sumb, 2);
        lrow[0] = lrow[0] * ala + suma;
        lrow[1] = lrow[1] * alb + sumb;
#pragma unroll
        for (int nb = 0; nb < 16; ++nb) {
            o[nb][0] *= ala; o[nb][1] *= ala;
            o[nb][2] *= alb; o[nb][3] *= alb;
        }

        uint32_t pah[4][4], pal[4][4];
#pragma unroll
        for (int j = 0; j < 4; ++j) {
            split2(sc[2 * j][0],     sc[2 * j][1],     pah[j][0], pal[j][0]);
            split2(sc[2 * j][2],     sc[2 * j][3],     pah[j][1], pal[j][1]);
            split2(sc[2 * j + 1][0], sc[2 * j + 1][1], pah[j][2], pal[j][2]);
            split2(sc[2 * j + 1][2], sc[2 * j + 1][3], pah[j][3], pal[j][3]);
        }

        uint32_t vbase = kvb + 2 * QT_B;
#pragma unroll 1
        for (int j = 0; j < 4; ++j) {
#pragma unroll
            for (int nb2 = 0; nb2 < 8; ++nb2) {
                uint32_t va = vbase + voff + j * 16 * VPADB + nb2 * 32;
                uint32_t h0, h1, h2, h3, l0, l1, l2, l3;
                ldsm4t(h0, h1, h2, h3, va);
                ldsm4t(l0, l1, l2, l3, va + VT_B);
                mma16816(o[2 * nb2],     pah[j][0], pah[j][1], pah[j][2], pah[j][3], h0, h1);
                mma16816(o[2 * nb2],     pah[j][0], pah[j][1], pah[j][2], pah[j][3], l0, l1);
                mma16816(o[2 * nb2],     pal[j][0], pal[j][1], pal[j][2], pal[j][3], h0, h1);
                mma16816(o[2 * nb2 + 1], pah[j][0], pah[j][1], pah[j][2], pah[j][3], h2, h3);
                mma16816(o[2 * nb2 + 1], pah[j][0], pah[j][1], pah[j][2], pah[j][3], l2, l3);
                mma16816(o[2 * nb2 + 1], pal[j][0], pal[j][1], pal[j][2], pal[j][3], h2, h3);
            }
        }
    }

    float inva = 1.0f / lrow[0], invb = 1.0f / lrow[1];
    int rowA = q0 + warp * 16 + rA;
    int rowB = rowA + 8;
#pragma unroll
    for (int nb = 0; nb < 16; ++nb) {
        int col = h * 128 + nb * 8 + colq;
        uint32_t hA, lA, hB, lB;
        split2(o[nb][0] * inva, o[nb][1] * inva, hA, lA);
        split2(o[nb][2] * invb, o[nb][3] * invb, hB, lB);
        *(uint32_t*)&Oh_g[(long)rowA * 2048 + col] = hA;
        *(uint32_t*)&Ol_g[(long)rowA * 2048 + col] = lA;
        *(uint32_t*)&Oh_g[(long)rowB * 2048 + col] = hB;
        *(uint32_t*)&Ol_g[(long)rowB * 2048 + col] = lB;
    }
}

// ---------------- launch ------------------------------------------------------
extern "C" void kernel_launch(void* const* d_in, const int* in_sizes, int n_in,
                              void* d_out, int out_size)
{
    const float* hidden   = (const float*)d_in[0];
    const int*   pos      = (const int*)d_in[1];
    const float* ln_w     = (const float*)d_in[3];
    const float* wq_a     = (const float*)d_in[4];
    const float* q_a_ln   = (const float*)d_in[5];
    const float* wq_b     = (const float*)d_in[6];
    const float* wkv_a    = (const float*)d_in[7];
    const float* kv_a_ln  = (const float*)d_in[8];
    const float* wkv_b    = (const float*)d_in[9];
    const float* wo       = (const float*)d_in[10];

    float* out   = (float*)d_out;
    float* k_out = out + (long)SEQ * HIDDEN;
    float* v_out = k_out + (long)NHEADS * SEQ * QKD;

    float *p_qackv, *p_q, *p_kv;
    cudaGetSymbolAddress((void**)&p_qackv, g_qackv);
    cudaGetSymbolAddress((void**)&p_q, g_q);
    cudaGetSymbolAddress((void**)&p_kv, g_kv);

    __nv_bfloat16 *h_hi, *h_lo, *qa_hi, *qa_lo, *ckvn_hi, *ckvn_lo, *attn_hi, *attn_lo;
    __nv_bfloat16 *qf_hi, *qf_lo, *k_hi, *k_lo, *v_hi, *v_lo;
    __nv_bfloat16 *wqkva_hi, *wqkva_lo, *wqb_hi, *wqb_lo, *wkvb_hi, *wkvb_lo, *wo_hi, *wo_lo;
    cudaGetSymbolAddress((void**)&h_hi, g_h_hi);       cudaGetSymbolAddress((void**)&h_lo, g_h_lo);
    cudaGetSymbolAddress((void**)&qa_hi, g_qa_hi);     cudaGetSymbolAddress((void**)&qa_lo, g_qa_lo);
    cudaGetSymbolAddress((void**)&ckvn_hi, g_ckvn_hi); cudaGetSymbolAddress((void**)&ckvn_lo, g_ckvn_lo);
    cudaGetSymbolAddress((void**)&attn_hi, g_attn_hi); cudaGetSymbolAddress((void**)&attn_lo, g_attn_lo);
    cudaGetSymbolAddress((void**)&qf_hi, g_qf_hi);     cudaGetSymbolAddress((void**)&qf_lo, g_qf_lo);
    cudaGetSymbolAddress((void**)&k_hi, g_k_hi);       cudaGetSymbolAddress((void**)&k_lo, g_k_lo);
    cudaGetSymbolAddress((void**)&v_hi, g_v_hi);       cudaGetSymbolAddress((void**)&v_lo, g_v_lo);
    cudaGetSymbolAddress((void**)&wqkva_hi, g_wqkva_hi); cudaGetSymbolAddress((void**)&wqkva_lo, g_wqkva_lo);
    cudaGetSymbolAddress((void**)&wqb_hi, g_wqb_hi);   cudaGetSymbolAddress((void**)&wqb_lo, g_wqb_lo);
    cudaGetSymbolAddress((void**)&wkvb_hi, g_wkvb_hi); cudaGetSymbolAddress((void**)&wkvb_lo, g_wkvb_lo);
    cudaGetSymbolAddress((void**)&wo_hi, g_wo_hi);     cudaGetSymbolAddress((void**)&wo_lo, g_wo_lo);

    cudaFuncSetAttribute(gemm_mma, cudaFuncAttributeMaxDynamicSharedMemorySize, GEMM_SMEM);
    cudaFuncSetAttribute(flash_mma, cudaFuncAttributeMaxDynamicSharedMemorySize, FLASH_SMEM);

    // weight conversions (wq_a and wkv_a fused into one [2112 x 5120] operand)
    cvt_b16<<<592, 256>>>(wq_a,  wqkva_hi, wqkva_lo, (long)QLORA * HIDDEN);
    cvt_b16<<<592, 256>>>(wkv_a, wqkva_hi + (long)QLORA * HIDDEN,
                                 wqkva_lo + (long)QLORA * HIDDEN, (long)576 * HIDDEN);
    cvt_b16<<<592, 256>>>(wq_b,  wqb_hi,  wqb_lo,  (long)3072 * QLORA);
    cvt_b16<<<592, 256>>>(wkv_b, wkvb_hi, wkvb_lo, (long)4096 * KVLORA);
    cvt_b16<<<592, 256>>>(wo,    wo_hi,   wo_lo,   (long)HIDDEN * 2048);

    rmsnorm_b16<<<SEQ, 256>>>(hidden, ln_w, h_hi, h_lo, HIDDEN, HIDDEN, HIDDEN);
    // fused q_a + ckv projection: [2048 x 2112] = h @ [wq_a; wkv_a]^T
    gemm_mma<<<dim3(17, SEQ / 128), 256, GEMM_SMEM>>>(
        h_hi, h_lo, HIDDEN, wqkva_hi, wqkva_lo, p_qackv, SEQ, QKVN, HIDDEN, nullptr, 0.f);
    rmsnorm_b16<<<SEQ, 256>>>(p_qackv, q_a_ln, qa_hi, qa_lo, QLORA, QKVN, QLORA);
    gemm_mma<<<dim3(3072 / 128, SEQ / 128), 256, GEMM_SMEM>>>(
        qa_hi, qa_lo, QLORA, wqb_hi, wqb_lo, p_q, SEQ, 3072, QLORA, nullptr, 0.f);
    rmsnorm_b16<<<SEQ, 256>>>(p_qackv + QLORA, kv_a_ln, ckvn_hi, ckvn_lo, KVLORA, QKVN, KVLORA);
    gemm_mma<<<dim3(4096 / 128, SEQ / 128), 256, GEMM_SMEM>>>(
        ckvn_hi, ckvn_lo, KVLORA, wkvb_hi, wkvb_lo, p_kv, SEQ, 4096, KVLORA, nullptr, 0.f);
    rope_scatter<<<SEQ, 256>>>(p_q, p_qackv, p_kv, pos, qf_hi, qf_lo,
                               k_out, k_hi, k_lo, v_out, v_hi, v_lo);
    flash_mma<<<dim3(SEQ / 64, NHEADS), 128, FLASH_SMEM>>>(
        qf_hi, qf_lo, k_hi, k_lo, v_hi, v_lo, attn_hi, attn_lo);
    gemm_mma<<<dim3(HIDDEN / 128, SEQ / 128), 256, GEMM_SMEM>>>(
        attn_hi, attn_lo, 2048, wo_hi, wo_lo, out, SEQ, HIDDEN, 2048,
        hidden, RESID_SCALE);
}